// round 9
// baseline (speedup 1.0000x reference)
#include <cuda_runtime.h>
#include <math.h>
#include <stdint.h>

#define BB 4
#define NN 4096
#define DD 128
#define KSPLIT 8                 // pv split-K factor
#define CHUNKS_PER_SPLIT (128 / KSPLIT)  // 16 chunks of 32

// ---------------- scratch (device globals; allocation-free) ----------------
__device__ float g_E[(size_t)BB * NN * NN];   // exp(S), tf32-rounded
__device__ float g_l[BB * NN];                // column sums over q
__device__ float g_Qt[(size_t)BB * NN * DD];  // RNA-tf32 rounded Q
__device__ float g_Kt[(size_t)BB * NN * DD];  // RNA-tf32 rounded K
__device__ float g_VT[(size_t)BB * DD * NN];  // V^T scaled by 1/l, tf32-rounded
__device__ float g_Po[(size_t)KSPLIT * BB * NN * DD];  // pv split partials

// ---------------- helpers ----------------
__device__ __forceinline__ uint32_t smem_u32(const void* p) {
    uint32_t a;
    asm("{ .reg .u64 t; cvta.to.shared.u64 t, %1; cvt.u32.u64 %0, t; }" : "=r"(a) : "l"(p));
    return a;
}
__device__ __forceinline__ float to_tf32(float x) {
    uint32_t u;
    asm("cvt.rna.tf32.f32 %0, %1;" : "=r"(u) : "f"(x));
    return __uint_as_float(u);
}

#define CP_ASYNC16(s, g) asm volatile("cp.async.cg.shared.global [%0], [%1], 16;" :: "r"(s), "l"(g))
#define CP_COMMIT()      asm volatile("cp.async.commit_group;" ::: "memory")
#define CP_WAIT(n)       asm volatile("cp.async.wait_group %0;" :: "n"(n) : "memory")

// m16n8k8 tf32 MMA, fp32 accumulate (baseline PTX, sm_80+)
__device__ __forceinline__ void mma_tf32(float* c, const uint32_t* a, const uint32_t* b) {
    asm volatile(
        "mma.sync.aligned.m16n8k8.row.col.f32.tf32.tf32.f32 "
        "{%0,%1,%2,%3}, {%4,%5,%6,%7}, {%8,%9}, {%0,%1,%2,%3};"
        : "+f"(c[0]), "+f"(c[1]), "+f"(c[2]), "+f"(c[3])
        : "r"(a[0]), "r"(a[1]), "r"(a[2]), "r"(a[3]), "r"(b[0]), "r"(b[1]));
}

// ldmatrix fragment loads (tf32-as-b16 trick: lane l -> row l>>2, f32 col l&3)
__device__ __forceinline__ void ldsm_x4(uint32_t* r, uint32_t addr) {
    asm volatile("ldmatrix.sync.aligned.m8n8.x4.shared.b16 {%0,%1,%2,%3}, [%4];"
                 : "=r"(r[0]), "=r"(r[1]), "=r"(r[2]), "=r"(r[3]) : "r"(addr));
}
__device__ __forceinline__ void ldsm_x2(uint32_t* r, uint32_t addr) {
    asm volatile("ldmatrix.sync.aligned.m8n8.x2.shared.b16 {%0,%1}, [%2];"
                 : "=r"(r[0]), "=r"(r[1]) : "r"(addr));
}

// SMEM tile: rows x 32 floats, row stride 36 floats (144B) -> conflict-free frags
__device__ __forceinline__ void load_t64_256(uint32_t sdst, const float* g, size_t rstride, int tid) {
#pragma unroll
    for (int i = 0; i < 2; i++) {
        int idx = i * 256 + tid;
        int row = idx >> 3, c4 = idx & 7;
        CP_ASYNC16(sdst + row * 144 + c4 * 16, g + (size_t)row * rstride + c4 * 4);
    }
}
__device__ __forceinline__ void load_t128_256(uint32_t sdst, const float* g, size_t rstride, int tid) {
#pragma unroll
    for (int i = 0; i < 4; i++) {
        int idx = i * 256 + tid;
        int row = idx >> 3, c4 = idx & 7;
        CP_ASYNC16(sdst + row * 144 + c4 * 16, g + (size_t)row * rstride + c4 * 4);
    }
}

// ---------------- small kernels ----------------
__global__ void cvt_kernel(const float* __restrict__ Q, const float* __restrict__ K) {
    size_t n = (size_t)BB * NN * DD;
    size_t i = (size_t)blockIdx.x * blockDim.x + threadIdx.x;
    if (i < n) {
        g_Qt[i] = to_tf32(Q[i]);
        g_Kt[i] = to_tf32(K[i]);
    }
    if (i < BB * NN) g_l[i] = 0.0f;
}
// VT[b][d][k] = rna(V[b][k][d] / l[b][k])
__global__ void vt_kernel(const float* __restrict__ V) {
    __shared__ float ts[32][33];
    int b = blockIdx.z, d0 = blockIdx.y * 32, k0 = blockIdx.x * 32;
    int tx = threadIdx.x, ty = threadIdx.y;
    const float* Vb = V + (size_t)b * NN * DD;
#pragma unroll
    for (int i = 0; i < 4; i++) {
        int r = ty + i * 8;
        ts[r][tx] = Vb[(size_t)(k0 + r) * DD + d0 + tx];
    }
    __syncthreads();
    float linv = 1.0f / g_l[b * NN + k0 + tx];
#pragma unroll
    for (int i = 0; i < 4; i++) {
        int d = ty + i * 8;
        g_VT[((size_t)b * DD + d0 + d) * NN + k0 + tx] = to_tf32(ts[tx][d] * linv);
    }
}
// O = sum of KSPLIT partials (deterministic order)
__global__ void reduce_kernel(float* __restrict__ O) {
    size_t i = ((size_t)blockIdx.x * blockDim.x + threadIdx.x) * 4;
    const size_t stride = (size_t)BB * NN * DD;
    if (i < stride) {
        float4 s = *(const float4*)(g_Po + i);
#pragma unroll
        for (int p = 1; p < KSPLIT; p++) {
            float4 t = *(const float4*)(g_Po + (size_t)p * stride + i);
            s.x += t.x; s.y += t.y; s.z += t.z; s.w += t.w;
        }
        *(float4*)(O + i) = s;
    }
}

// Shared tile geometry: A 64 rows, B 128 rows, 32 cols, stride 36 floats
#define TILEA (64 * 36 * 4)    // 9216
#define TILEBB (128 * 36 * 4)  // 18432
#define SMBOTH (2 * (TILEA + TILEBB))  // 55296

// ---------------- kernel 1: E = exp(QK^T/sqrt(D)), l = colsum(E) ----------------
// grid (32 kt, 64 qt, 4 b), 256 threads (8 warps, 2x4), tile 64q x 128k,
// warp 32x32, K(=D)=128 in 4 chunks, 2-stage single-sync, occ 3.
__global__ __launch_bounds__(256, 3) void qk_exp_kernel() {
    const int b = blockIdx.z, qb = blockIdx.y * 64, kb = blockIdx.x * 128;
    const int tid = threadIdx.x, lane = tid & 31, wid = tid >> 5;
    const int wm = wid >> 2, wn = wid & 3;

    extern __shared__ __align__(16) char dyn[];
    uint32_t sbase = smem_u32(dyn);
    uint32_t sA[2] = { sbase, sbase + TILEA };
    uint32_t sB[2] = { sbase + 2 * TILEA, sbase + 2 * TILEA + TILEBB };

    const float* Qg = g_Qt + ((size_t)b * NN + qb) * DD;
    const float* Kg = g_Kt + ((size_t)b * NN + kb) * DD;

    const int lr = lane & 7, lg = (lane >> 3) & 1, lh = lane >> 4;
    uint32_t a_off[2], b_off[4];
#pragma unroll
    for (int i = 0; i < 2; i++)
        a_off[i] = (uint32_t)(wm * 32 + i * 16 + lr + lg * 8) * 144 + (uint32_t)lh * 16;
#pragma unroll
    for (int j = 0; j < 4; j++)
        b_off[j] = (uint32_t)(wn * 32 + j * 8 + lr) * 144 + (uint32_t)lg * 16;

    float acc[2][4][4];
#pragma unroll
    for (int i = 0; i < 2; i++)
#pragma unroll
        for (int j = 0; j < 4; j++)
#pragma unroll
            for (int t = 0; t < 4; t++) acc[i][j][t] = 0.0f;

    load_t64_256(sA[0], Qg, DD, tid);
    load_t128_256(sB[0], Kg, DD, tid);
    CP_COMMIT();

#pragma unroll 1
    for (int c = 0; c < 4; c++) {
        CP_WAIT(0);
        __syncthreads();
        if (c + 1 < 4) {
            load_t64_256(sA[(c + 1) & 1], Qg + (c + 1) * 32, DD, tid);
            load_t128_256(sB[(c + 1) & 1], Kg + (c + 1) * 32, DD, tid);
            CP_COMMIT();
        }
        const uint32_t Ab = sA[c & 1], Bb = sB[c & 1];
#pragma unroll
        for (int ks = 0; ks < 4; ks++) {
            const uint32_t k0b = ks * 32;
            uint32_t af[2][4], bf[4][2];
#pragma unroll
            for (int i = 0; i < 2; i++) ldsm_x4(af[i], Ab + a_off[i] + k0b);
#pragma unroll
            for (int j = 0; j < 4; j++) ldsm_x2(bf[j], Bb + b_off[j] + k0b);
#pragma unroll
            for (int i = 0; i < 2; i++)
#pragma unroll
                for (int j = 0; j < 4; j++) mma_tf32(acc[i][j], af[i], bf[j]);
        }
    }

    const float SCALE = 0.08838834764831845f;
    float csum[4][2];
#pragma unroll
    for (int j = 0; j < 4; j++) { csum[j][0] = 0.0f; csum[j][1] = 0.0f; }

#pragma unroll
    for (int i = 0; i < 2; i++) {
        const int row0 = qb + wm * 32 + i * 16 + (lane >> 2);
#pragma unroll
        for (int j = 0; j < 4; j++) {
            float e0 = to_tf32(__expf(acc[i][j][0] * SCALE));
            float e1 = to_tf32(__expf(acc[i][j][1] * SCALE));
            float e2 = to_tf32(__expf(acc[i][j][2] * SCALE));
            float e3 = to_tf32(__expf(acc[i][j][3] * SCALE));
            const int col = kb + wn * 32 + j * 8 + (lane & 3) * 2;
            float2* p0 = (float2*)(g_E + ((size_t)b * NN + row0) * NN + col);
            float2* p1 = (float2*)(g_E + ((size_t)b * NN + row0 + 8) * NN + col);
            *p0 = make_float2(e0, e1);
            *p1 = make_float2(e2, e3);
            csum[j][0] += e0 + e2;
            csum[j][1] += e1 + e3;
        }
    }
#pragma unroll
    for (int j = 0; j < 4; j++) {
#pragma unroll
        for (int p = 0; p < 2; p++) {
            float v = csum[j][p];
            v += __shfl_xor_sync(0xffffffffu, v, 4);
            v += __shfl_xor_sync(0xffffffffu, v, 8);
            v += __shfl_xor_sync(0xffffffffu, v, 16);
            if (lane < 4)
                atomicAdd(&g_l[b * NN + kb + wn * 32 + j * 8 + lane * 2 + p], v);
        }
    }
}

// ---------------- kernel 2: partial O = E_norm @ V over one K-split ----------------
// grid (64 qt, KSPLIT, 4 b), 256 threads (8 warps, 2x4), tile 64q x 128d,
// warp 32x32, 16 chunks of 32, 2-stage single-sync, occ 3.
__global__ __launch_bounds__(256, 3) void pv_kernel() {
    const int b = blockIdx.z, split = blockIdx.y, qb = blockIdx.x * 64;
    const int tid = threadIdx.x, lane = tid & 31, wid = tid >> 5;
    const int wm = wid >> 2, wn = wid & 3;
    const int c0 = split * CHUNKS_PER_SPLIT;

    extern __shared__ __align__(16) char dyn[];
    uint32_t sbase = smem_u32(dyn);
    uint32_t sA[2] = { sbase, sbase + TILEA };
    uint32_t sB[2] = { sbase + 2 * TILEA, sbase + 2 * TILEA + TILEBB };

    const float* Eg = g_E + ((size_t)b * NN + qb) * NN;
    const float* Vg = g_VT + (size_t)b * DD * NN;

    const int lr = lane & 7, lg = (lane >> 3) & 1, lh = lane >> 4;
    uint32_t a_off[2], b_off[4];
#pragma unroll
    for (int i = 0; i < 2; i++)
        a_off[i] = (uint32_t)(wm * 32 + i * 16 + lr + lg * 8) * 144 + (uint32_t)lh * 16;
#pragma unroll
    for (int j = 0; j < 4; j++)
        b_off[j] = (uint32_t)(wn * 32 + j * 8 + lr) * 144 + (uint32_t)lg * 16;

    float acc[2][4][4];
#pragma unroll
    for (int i = 0; i < 2; i++)
#pragma unroll
        for (int j = 0; j < 4; j++)
#pragma unroll
            for (int t = 0; t < 4; t++) acc[i][j][t] = 0.0f;

    load_t64_256(sA[0], Eg + (size_t)c0 * 32, NN, tid);
    load_t128_256(sB[0], Vg + (size_t)c0 * 32, NN, tid);
    CP_COMMIT();

#pragma unroll 1
    for (int c = 0; c < CHUNKS_PER_SPLIT; c++) {
        CP_WAIT(0);
        __syncthreads();
        if (c + 1 < CHUNKS_PER_SPLIT) {
            load_t64_256(sA[(c + 1) & 1], Eg + (size_t)(c0 + c + 1) * 32, NN, tid);
            load_t128_256(sB[(c + 1) & 1], Vg + (size_t)(c0 + c + 1) * 32, NN, tid);
            CP_COMMIT();
        }
        const uint32_t Ab = sA[c & 1], Bb = sB[c & 1];
#pragma unroll
        for (int ks = 0; ks < 4; ks++) {
            const uint32_t k0b = ks * 32;
            uint32_t af[2][4], bf[4][2];
#pragma unroll
            for (int i = 0; i < 2; i++) ldsm_x4(af[i], Ab + a_off[i] + k0b);
#pragma unroll
            for (int j = 0; j < 4; j++) ldsm_x2(bf[j], Bb + b_off[j] + k0b);
#pragma unroll
            for (int i = 0; i < 2; i++)
#pragma unroll
                for (int j = 0; j < 4; j++) mma_tf32(acc[i][j], af[i], bf[j]);
        }
    }

    float* Po = g_Po + (size_t)split * BB * NN * DD;
#pragma unroll
    for (int i = 0; i < 2; i++) {
        const int row0 = qb + wm * 32 + i * 16 + (lane >> 2);
#pragma unroll
        for (int j = 0; j < 4; j++) {
            const int col = wn * 32 + j * 8 + (lane & 3) * 2;
            float2* p0 = (float2*)(Po + ((size_t)b * NN + row0) * DD + col);
            float2* p1 = (float2*)(Po + ((size_t)b * NN + row0 + 8) * DD + col);
            *p0 = make_float2(acc[i][j][0], acc[i][j][1]);
            *p1 = make_float2(acc[i][j][2], acc[i][j][3]);
        }
    }
}

// ---------------- launch ----------------
extern "C" void kernel_launch(void* const* d_in, const int* in_sizes, int n_in,
                              void* d_out, int out_size) {
    const float* q = (const float*)d_in[0];
    const float* k = (const float*)d_in[1];
    const float* v = (const float*)d_in[2];
    float* out = (float*)d_out;

    cudaFuncSetAttribute(qk_exp_kernel, cudaFuncAttributeMaxDynamicSharedMemorySize, SMBOTH);
    cudaFuncSetAttribute(pv_kernel, cudaFuncAttributeMaxDynamicSharedMemorySize, SMBOTH);

    size_t nqk = (size_t)BB * NN * DD;
    cvt_kernel<<<(unsigned)((nqk + 255) / 256), 256>>>(q, k);

    qk_exp_kernel<<<dim3(NN / 128, NN / 64, BB), 256, SMBOTH>>>();

    vt_kernel<<<dim3(NN / 32, DD / 32, BB), dim3(32, 8)>>>(v);

    pv_kernel<<<dim3(NN / 64, KSPLIT, BB), 256, SMBOTH>>>();

    size_t nout = (size_t)BB * NN * DD;
    reduce_kernel<<<(unsigned)((nout / 4 + 255) / 256), 256>>>(out);
}

// round 10
// speedup vs baseline: 1.0741x; 1.0741x over previous
#include <cuda_runtime.h>
#include <math.h>
#include <stdint.h>

#define BB 4
#define NN 4096
#define DD 128
#define KSPLIT 8                 // pv split-K factor
#define CHUNKS_PER_SPLIT (128 / KSPLIT)  // 16 chunks of 32

// ---------------- scratch (device globals; allocation-free) ----------------
__device__ float g_E[(size_t)BB * NN * NN];   // exp(S), tf32-rounded
__device__ float g_l[BB * NN];                // column sums over q
__device__ float g_Qt[(size_t)BB * NN * DD];  // RNA-tf32 rounded Q
__device__ float g_Kt[(size_t)BB * NN * DD];  // RNA-tf32 rounded K
__device__ float g_VT[(size_t)BB * DD * NN];  // V^T scaled by 1/l, tf32-rounded
__device__ float g_Po[(size_t)KSPLIT * BB * NN * DD];  // pv split partials

// ---------------- helpers ----------------
__device__ __forceinline__ uint32_t smem_u32(const void* p) {
    uint32_t a;
    asm("{ .reg .u64 t; cvta.to.shared.u64 t, %1; cvt.u32.u64 %0, t; }" : "=r"(a) : "l"(p));
    return a;
}
__device__ __forceinline__ float to_tf32(float x) {
    uint32_t u;
    asm("cvt.rna.tf32.f32 %0, %1;" : "=r"(u) : "f"(x));
    return __uint_as_float(u);
}

// exp(s/sqrt(128)) on the FMA/ALU pipes (no MUFU).
// y = s * log2(e)/sqrt(128); 2^y = 2^n * 2^f, n=rne(y), f in [-0.5,0.5].
// deg-5 Taylor for 2^f: max rel err ~2.4e-6 (absorbed by tf32 rounding after).
__device__ __forceinline__ float exp_scaled(float s) {
    const float C = 0.12753785771239599f;  // log2(e)/sqrt(128)
    const float MAGIC = 12582912.0f;       // 2^23 + 2^22
    float y = s * C;
    float t = y + MAGIC;
    int ni = __float_as_int(t) - __float_as_int(MAGIC);  // rne(y) as int
    float f = y - (t - MAGIC);                           // y - rne(y)
    float p = 1.33335581e-3f;
    p = fmaf(p, f, 9.61812911e-3f);
    p = fmaf(p, f, 5.55041087e-2f);
    p = fmaf(p, f, 2.40226507e-1f);
    p = fmaf(p, f, 6.93147181e-1f);
    p = fmaf(p, f, 1.0f);
    float sc = __int_as_float((ni + 127) << 23);
    return p * sc;
}

#define CP_ASYNC16(s, g) asm volatile("cp.async.cg.shared.global [%0], [%1], 16;" :: "r"(s), "l"(g))
#define CP_COMMIT()      asm volatile("cp.async.commit_group;" ::: "memory")
#define CP_WAIT(n)       asm volatile("cp.async.wait_group %0;" :: "n"(n) : "memory")

// m16n8k8 tf32 MMA, fp32 accumulate (baseline PTX, sm_80+)
__device__ __forceinline__ void mma_tf32(float* c, const uint32_t* a, const uint32_t* b) {
    asm volatile(
        "mma.sync.aligned.m16n8k8.row.col.f32.tf32.tf32.f32 "
        "{%0,%1,%2,%3}, {%4,%5,%6,%7}, {%8,%9}, {%0,%1,%2,%3};"
        : "+f"(c[0]), "+f"(c[1]), "+f"(c[2]), "+f"(c[3])
        : "r"(a[0]), "r"(a[1]), "r"(a[2]), "r"(a[3]), "r"(b[0]), "r"(b[1]));
}

// ldmatrix fragment loads (tf32-as-b16 trick: lane l -> row l>>2, f32 col l&3)
__device__ __forceinline__ void ldsm_x4(uint32_t* r, uint32_t addr) {
    asm volatile("ldmatrix.sync.aligned.m8n8.x4.shared.b16 {%0,%1,%2,%3}, [%4];"
                 : "=r"(r[0]), "=r"(r[1]), "=r"(r[2]), "=r"(r[3]) : "r"(addr));
}
__device__ __forceinline__ void ldsm_x2(uint32_t* r, uint32_t addr) {
    asm volatile("ldmatrix.sync.aligned.m8n8.x2.shared.b16 {%0,%1}, [%2];"
                 : "=r"(r[0]), "=r"(r[1]) : "r"(addr));
}

// SMEM tile: rows x 32 floats, row stride 36 floats (144B) -> conflict-free frags
__device__ __forceinline__ void load_t128_256(uint32_t sdst, const float* g, size_t rstride, int tid) {
#pragma unroll
    for (int i = 0; i < 4; i++) {
        int idx = i * 256 + tid;
        int row = idx >> 3, c4 = idx & 7;
        CP_ASYNC16(sdst + row * 144 + c4 * 16, g + (size_t)row * rstride + c4 * 4);
    }
}
__device__ __forceinline__ void load_t64_128(uint32_t sdst, const float* g, size_t rstride, int tid) {
#pragma unroll
    for (int i = 0; i < 4; i++) {
        int idx = i * 128 + tid;
        int row = idx >> 3, c4 = idx & 7;
        CP_ASYNC16(sdst + row * 144 + c4 * 16, g + (size_t)row * rstride + c4 * 4);
    }
}
__device__ __forceinline__ void load_t128_128(uint32_t sdst, const float* g, size_t rstride, int tid) {
#pragma unroll
    for (int i = 0; i < 8; i++) {
        int idx = i * 128 + tid;
        int row = idx >> 3, c4 = idx & 7;
        CP_ASYNC16(sdst + row * 144 + c4 * 16, g + (size_t)row * rstride + c4 * 4);
    }
}

// ---------------- small kernels ----------------
__global__ void cvt_kernel(const float* __restrict__ Q, const float* __restrict__ K) {
    size_t n = (size_t)BB * NN * DD;
    size_t i = (size_t)blockIdx.x * blockDim.x + threadIdx.x;
    if (i < n) {
        g_Qt[i] = to_tf32(Q[i]);
        g_Kt[i] = to_tf32(K[i]);
    }
    if (i < BB * NN) g_l[i] = 0.0f;
}
// VT[b][d][k] = rna(V[b][k][d] / l[b][k])
__global__ void vt_kernel(const float* __restrict__ V) {
    __shared__ float ts[32][33];
    int b = blockIdx.z, d0 = blockIdx.y * 32, k0 = blockIdx.x * 32;
    int tx = threadIdx.x, ty = threadIdx.y;
    const float* Vb = V + (size_t)b * NN * DD;
#pragma unroll
    for (int i = 0; i < 4; i++) {
        int r = ty + i * 8;
        ts[r][tx] = Vb[(size_t)(k0 + r) * DD + d0 + tx];
    }
    __syncthreads();
    float linv = 1.0f / g_l[b * NN + k0 + tx];
#pragma unroll
    for (int i = 0; i < 4; i++) {
        int d = ty + i * 8;
        g_VT[((size_t)b * DD + d0 + d) * NN + k0 + tx] = to_tf32(ts[tx][d] * linv);
    }
}
// O = sum of KSPLIT partials (deterministic order)
__global__ void reduce_kernel(float* __restrict__ O) {
    size_t i = ((size_t)blockIdx.x * blockDim.x + threadIdx.x) * 4;
    const size_t stride = (size_t)BB * NN * DD;
    if (i < stride) {
        float4 s = *(const float4*)(g_Po + i);
#pragma unroll
        for (int p = 1; p < KSPLIT; p++) {
            float4 t = *(const float4*)(g_Po + (size_t)p * stride + i);
            s.x += t.x; s.y += t.y; s.z += t.z; s.w += t.w;
        }
        *(float4*)(O + i) = s;
    }
}

// ---------------- kernel 1: E = exp(QK^T/sqrt(D)), l = colsum(E) ----------------
// grid (32 kt, 32 qt, 4 b), 256 threads (8 warps, 2x4), tile 128x128, K=128 in 4 chunks.
#define TILEB (128 * 36 * 4)  // 18432
#define SM1 (4 * TILEB)       // 73728
__global__ __launch_bounds__(256, 2) void qk_exp_kernel() {
    const int b = blockIdx.z, qb = blockIdx.y * 128, kb = blockIdx.x * 128;
    const int tid = threadIdx.x, lane = tid & 31, wid = tid >> 5;
    const int wm = wid >> 2, wn = wid & 3;

    extern __shared__ __align__(16) char dyn[];
    uint32_t sbase = smem_u32(dyn);
    uint32_t sA[2] = { sbase, sbase + TILEB };
    uint32_t sB[2] = { sbase + 2 * TILEB, sbase + 3 * TILEB };

    const float* Qg = g_Qt + ((size_t)b * NN + qb) * DD;
    const float* Kg = g_Kt + ((size_t)b * NN + kb) * DD;

    const int lr = lane & 7, lg = (lane >> 3) & 1, lh = lane >> 4;
    uint32_t a_off[4], b_off[4];
#pragma unroll
    for (int i = 0; i < 4; i++)
        a_off[i] = (uint32_t)(wm * 64 + i * 16 + lr + lg * 8) * 144 + (uint32_t)lh * 16;
#pragma unroll
    for (int j = 0; j < 4; j++)
        b_off[j] = (uint32_t)(wn * 32 + j * 8 + lr) * 144 + (uint32_t)lg * 16;

    float acc[4][4][4];
#pragma unroll
    for (int i = 0; i < 4; i++)
#pragma unroll
        for (int j = 0; j < 4; j++)
#pragma unroll
            for (int t = 0; t < 4; t++) acc[i][j][t] = 0.0f;

    load_t128_256(sA[0], Qg, DD, tid);
    load_t128_256(sB[0], Kg, DD, tid);
    CP_COMMIT();

#pragma unroll 1
    for (int c = 0; c < 4; c++) {
        CP_WAIT(0);
        __syncthreads();
        if (c + 1 < 4) {
            load_t128_256(sA[(c + 1) & 1], Qg + (c + 1) * 32, DD, tid);
            load_t128_256(sB[(c + 1) & 1], Kg + (c + 1) * 32, DD, tid);
            CP_COMMIT();
        }
        const uint32_t Ab = sA[c & 1], Bb = sB[c & 1];
#pragma unroll
        for (int ks = 0; ks < 4; ks++) {
            const uint32_t k0b = ks * 32;
            uint32_t af[4][4], bf[4][2];
#pragma unroll
            for (int i = 0; i < 4; i++) ldsm_x4(af[i], Ab + a_off[i] + k0b);
#pragma unroll
            for (int j = 0; j < 4; j++) ldsm_x2(bf[j], Bb + b_off[j] + k0b);
#pragma unroll
            for (int i = 0; i < 4; i++)
#pragma unroll
                for (int j = 0; j < 4; j++) mma_tf32(acc[i][j], af[i], bf[j]);
        }
    }

    float csum[4][2];
#pragma unroll
    for (int j = 0; j < 4; j++) { csum[j][0] = 0.0f; csum[j][1] = 0.0f; }

#pragma unroll
    for (int i = 0; i < 4; i++) {
        const int row0 = qb + wm * 64 + i * 16 + (lane >> 2);
#pragma unroll
        for (int j = 0; j < 4; j++) {
            float e0 = to_tf32(exp_scaled(acc[i][j][0]));
            float e1 = to_tf32(exp_scaled(acc[i][j][1]));
            float e2 = to_tf32(exp_scaled(acc[i][j][2]));
            float e3 = to_tf32(exp_scaled(acc[i][j][3]));
            const int col = kb + wn * 32 + j * 8 + (lane & 3) * 2;
            float2* p0 = (float2*)(g_E + ((size_t)b * NN + row0) * NN + col);
            float2* p1 = (float2*)(g_E + ((size_t)b * NN + row0 + 8) * NN + col);
            *p0 = make_float2(e0, e1);
            *p1 = make_float2(e2, e3);
            csum[j][0] += e0 + e2;
            csum[j][1] += e1 + e3;
        }
    }
#pragma unroll
    for (int j = 0; j < 4; j++) {
#pragma unroll
        for (int p = 0; p < 2; p++) {
            float v = csum[j][p];
            v += __shfl_xor_sync(0xffffffffu, v, 4);
            v += __shfl_xor_sync(0xffffffffu, v, 8);
            v += __shfl_xor_sync(0xffffffffu, v, 16);
            if (lane < 4)
                atomicAdd(&g_l[b * NN + kb + wn * 32 + j * 8 + lane * 2 + p], v);
        }
    }
}

// ---------------- kernel 2: partial O = E_norm @ V over one K-split ----------------
// grid (64 qt, KSPLIT, 4 b), 128 threads (4 warps), tile 64(q) x 128(d), warp 64x32,
// 16 chunks of 32, 2-stage, single sync per iteration, occ 4.
#define TILEB64 (64 * 36 * 4)          // 9216
#define SM2 (2 * TILEB64 + 2 * TILEB)  // 55296
__global__ __launch_bounds__(128, 4) void pv_kernel() {
    const int b = blockIdx.z, split = blockIdx.y, qb = blockIdx.x * 64;
    const int tid = threadIdx.x, lane = tid & 31, wn = tid >> 5;
    const int c0 = split * CHUNKS_PER_SPLIT;

    extern __shared__ __align__(16) char dyn[];
    uint32_t sbase = smem_u32(dyn);
    uint32_t sA[2] = { sbase, sbase + TILEB64 };
    uint32_t sB[2] = { sbase + 2 * TILEB64, sbase + 2 * TILEB64 + TILEB };

    const float* Eg = g_E + ((size_t)b * NN + qb) * NN;
    const float* Vg = g_VT + (size_t)b * DD * NN;

    const int lr = lane & 7, lg = (lane >> 3) & 1, lh = lane >> 4;
    uint32_t a_off[4], b_off[4];
#pragma unroll
    for (int i = 0; i < 4; i++)
        a_off[i] = (uint32_t)(i * 16 + lr + lg * 8) * 144 + (uint32_t)lh * 16;
#pragma unroll
    for (int j = 0; j < 4; j++)
        b_off[j] = (uint32_t)(wn * 32 + j * 8 + lr) * 144 + (uint32_t)lg * 16;

    float acc[4][4][4];
#pragma unroll
    for (int i = 0; i < 4; i++)
#pragma unroll
        for (int j = 0; j < 4; j++)
#pragma unroll
            for (int t = 0; t < 4; t++) acc[i][j][t] = 0.0f;

    load_t64_128(sA[0], Eg + (size_t)c0 * 32, NN, tid);
    load_t128_128(sB[0], Vg + (size_t)c0 * 32, NN, tid);
    CP_COMMIT();

#pragma unroll 1
    for (int c = 0; c < CHUNKS_PER_SPLIT; c++) {
        CP_WAIT(0);
        __syncthreads();
        if (c + 1 < CHUNKS_PER_SPLIT) {
            load_t64_128(sA[(c + 1) & 1], Eg + (size_t)(c0 + c + 1) * 32, NN, tid);
            load_t128_128(sB[(c + 1) & 1], Vg + (size_t)(c0 + c + 1) * 32, NN, tid);
            CP_COMMIT();
        }
        const uint32_t Ab = sA[c & 1], Bb = sB[c & 1];
#pragma unroll
        for (int ks = 0; ks < 4; ks++) {
            const uint32_t k0b = ks * 32;
            uint32_t af[4][4], bf[4][2];
#pragma unroll
            for (int i = 0; i < 4; i++) ldsm_x4(af[i], Ab + a_off[i] + k0b);
#pragma unroll
            for (int j = 0; j < 4; j++) ldsm_x2(bf[j], Bb + b_off[j] + k0b);
#pragma unroll
            for (int i = 0; i < 4; i++)
#pragma unroll
                for (int j = 0; j < 4; j++) mma_tf32(acc[i][j], af[i], bf[j]);
        }
    }

    float* Po = g_Po + (size_t)split * BB * NN * DD;
#pragma unroll
    for (int i = 0; i < 4; i++) {
        const int row0 = qb + i * 16 + (lane >> 2);
#pragma unroll
        for (int j = 0; j < 4; j++) {
            const int col = wn * 32 + j * 8 + (lane & 3) * 2;
            float2* p0 = (float2*)(Po + ((size_t)b * NN + row0) * DD + col);
            float2* p1 = (float2*)(Po + ((size_t)b * NN + row0 + 8) * DD + col);
            *p0 = make_float2(acc[i][j][0], acc[i][j][1]);
            *p1 = make_float2(acc[i][j][2], acc[i][j][3]);
        }
    }
}

// ---------------- launch ----------------
extern "C" void kernel_launch(void* const* d_in, const int* in_sizes, int n_in,
                              void* d_out, int out_size) {
    const float* q = (const float*)d_in[0];
    const float* k = (const float*)d_in[1];
    const float* v = (const float*)d_in[2];
    float* out = (float*)d_out;

    cudaFuncSetAttribute(qk_exp_kernel, cudaFuncAttributeMaxDynamicSharedMemorySize, SM1);
    cudaFuncSetAttribute(pv_kernel, cudaFuncAttributeMaxDynamicSharedMemorySize, SM2);

    size_t nqk = (size_t)BB * NN * DD;
    cvt_kernel<<<(unsigned)((nqk + 255) / 256), 256>>>(q, k);

    qk_exp_kernel<<<dim3(NN / 128, NN / 128, BB), 256, SM1>>>();

    vt_kernel<<<dim3(NN / 32, DD / 32, BB), dim3(32, 8)>>>(v);

    pv_kernel<<<dim3(NN / 64, KSPLIT, BB), 128, SM2>>>();

    size_t nout = (size_t)BB * NN * DD;
    reduce_kernel<<<(unsigned)((nout / 4 + 255) / 256), 256>>>(out);
}

// round 11
// speedup vs baseline: 1.3257x; 1.2343x over previous
#include <cuda_runtime.h>
#include <cuda_fp16.h>
#include <math.h>
#include <stdint.h>

#define BB 4
#define NN 4096
#define DD 128
#define KSPLIT 8                 // pv split-K factor
#define CHUNKS_PER_SPLIT (128 / KSPLIT)  // 16 chunks of 32

// ---------------- scratch (device globals; allocation-free) ----------------
__device__ __half g_Eh[(size_t)BB * NN * NN];  // exp(S), fp16 (134 MB)
__device__ float g_l[BB * NN];                 // column sums over q (of fp16-rounded E)
__device__ float g_Qt[(size_t)BB * NN * DD];   // RNA-tf32 rounded Q
__device__ float g_Kt[(size_t)BB * NN * DD];   // RNA-tf32 rounded K
__device__ __half g_VTh[(size_t)BB * DD * NN]; // V^T scaled by 1/l, fp16
__device__ float g_Po[(size_t)KSPLIT * BB * NN * DD];  // pv split partials

// ---------------- helpers ----------------
__device__ __forceinline__ uint32_t smem_u32(const void* p) {
    uint32_t a;
    asm("{ .reg .u64 t; cvta.to.shared.u64 t, %1; cvt.u32.u64 %0, t; }" : "=r"(a) : "l"(p));
    return a;
}
__device__ __forceinline__ float to_tf32(float x) {
    uint32_t u;
    asm("cvt.rna.tf32.f32 %0, %1;" : "=r"(u) : "f"(x));
    return __uint_as_float(u);
}

#define CP_ASYNC16(s, g) asm volatile("cp.async.cg.shared.global [%0], [%1], 16;" :: "r"(s), "l"(g))
#define CP_COMMIT()      asm volatile("cp.async.commit_group;" ::: "memory")
#define CP_WAIT(n)       asm volatile("cp.async.wait_group %0;" :: "n"(n) : "memory")

// m16n8k8 tf32 MMA (qk)
__device__ __forceinline__ void mma_tf32(float* c, const uint32_t* a, const uint32_t* b) {
    asm volatile(
        "mma.sync.aligned.m16n8k8.row.col.f32.tf32.tf32.f32 "
        "{%0,%1,%2,%3}, {%4,%5,%6,%7}, {%8,%9}, {%0,%1,%2,%3};"
        : "+f"(c[0]), "+f"(c[1]), "+f"(c[2]), "+f"(c[3])
        : "r"(a[0]), "r"(a[1]), "r"(a[2]), "r"(a[3]), "r"(b[0]), "r"(b[1]));
}
// m16n8k16 fp16 MMA, fp32 accumulate (pv)
__device__ __forceinline__ void mma_f16(float* c, const uint32_t* a, const uint32_t* b) {
    asm volatile(
        "mma.sync.aligned.m16n8k16.row.col.f32.f16.f16.f32 "
        "{%0,%1,%2,%3}, {%4,%5,%6,%7}, {%8,%9}, {%0,%1,%2,%3};"
        : "+f"(c[0]), "+f"(c[1]), "+f"(c[2]), "+f"(c[3])
        : "r"(a[0]), "r"(a[1]), "r"(a[2]), "r"(a[3]), "r"(b[0]), "r"(b[1]));
}

__device__ __forceinline__ void ldsm_x4(uint32_t* r, uint32_t addr) {
    asm volatile("ldmatrix.sync.aligned.m8n8.x4.shared.b16 {%0,%1,%2,%3}, [%4];"
                 : "=r"(r[0]), "=r"(r[1]), "=r"(r[2]), "=r"(r[3]) : "r"(addr));
}
__device__ __forceinline__ void ldsm_x2(uint32_t* r, uint32_t addr) {
    asm volatile("ldmatrix.sync.aligned.m8n8.x2.shared.b16 {%0,%1}, [%2];"
                 : "=r"(r[0]), "=r"(r[1]) : "r"(addr));
}

// fp32 tiles (qk): rows x 32 floats, row stride 36 floats (144B)
__device__ __forceinline__ void load_t128_256(uint32_t sdst, const float* g, size_t rstride, int tid) {
#pragma unroll
    for (int i = 0; i < 4; i++) {
        int idx = i * 256 + tid;
        int row = idx >> 3, c4 = idx & 7;
        CP_ASYNC16(sdst + row * 144 + c4 * 16, g + (size_t)row * rstride + c4 * 4);
    }
}
// fp16 tiles (pv): rows x 32 halves (64B data), row stride 80B (conflict-free ldsm)
__device__ __forceinline__ void load_h64_128(uint32_t sdst, const __half* g, size_t rstride, int tid) {
#pragma unroll
    for (int i = 0; i < 2; i++) {
        int idx = i * 128 + tid;   // 256 chunks of 16B
        int row = idx >> 2, c4 = idx & 3;
        CP_ASYNC16(sdst + row * 80 + c4 * 16, g + (size_t)row * rstride + c4 * 8);
    }
}
__device__ __forceinline__ void load_h128_128(uint32_t sdst, const __half* g, size_t rstride, int tid) {
#pragma unroll
    for (int i = 0; i < 4; i++) {
        int idx = i * 128 + tid;   // 512 chunks of 16B
        int row = idx >> 2, c4 = idx & 3;
        CP_ASYNC16(sdst + row * 80 + c4 * 16, g + (size_t)row * rstride + c4 * 8);
    }
}

// ---------------- small kernels ----------------
__global__ void cvt_kernel(const float* __restrict__ Q, const float* __restrict__ K) {
    size_t n = (size_t)BB * NN * DD;
    size_t i = (size_t)blockIdx.x * blockDim.x + threadIdx.x;
    if (i < n) {
        g_Qt[i] = to_tf32(Q[i]);
        g_Kt[i] = to_tf32(K[i]);
    }
    if (i < BB * NN) g_l[i] = 0.0f;
}
// VT[b][d][k] = fp16(V[b][k][d] / l[b][k])
__global__ void vt_kernel(const float* __restrict__ V) {
    __shared__ float ts[32][33];
    int b = blockIdx.z, d0 = blockIdx.y * 32, k0 = blockIdx.x * 32;
    int tx = threadIdx.x, ty = threadIdx.y;
    const float* Vb = V + (size_t)b * NN * DD;
#pragma unroll
    for (int i = 0; i < 4; i++) {
        int r = ty + i * 8;
        ts[r][tx] = Vb[(size_t)(k0 + r) * DD + d0 + tx];
    }
    __syncthreads();
    float linv = 1.0f / g_l[b * NN + k0 + tx];
#pragma unroll
    for (int i = 0; i < 4; i++) {
        int d = ty + i * 8;
        g_VTh[((size_t)b * DD + d0 + d) * NN + k0 + tx] = __float2half_rn(ts[tx][d] * linv);
    }
}
// O = sum of KSPLIT partials (deterministic order)
__global__ void reduce_kernel(float* __restrict__ O) {
    size_t i = ((size_t)blockIdx.x * blockDim.x + threadIdx.x) * 4;
    const size_t stride = (size_t)BB * NN * DD;
    if (i < stride) {
        float4 s = *(const float4*)(g_Po + i);
#pragma unroll
        for (int p = 1; p < KSPLIT; p++) {
            float4 t = *(const float4*)(g_Po + (size_t)p * stride + i);
            s.x += t.x; s.y += t.y; s.z += t.z; s.w += t.w;
        }
        *(float4*)(O + i) = s;
    }
}

// ---------------- kernel 1: E = exp(QK^T/sqrt(D)) fp16, l = colsum(E) ----------------
// grid (32 kt, 32 qt, 4 b), 256 threads (8 warps, 2x4), tile 128x128, K=128 in 4 chunks.
#define TILEB (128 * 36 * 4)  // 18432
#define SM1 (4 * TILEB)       // 73728
__global__ __launch_bounds__(256, 2) void qk_exp_kernel() {
    const int b = blockIdx.z, qb = blockIdx.y * 128, kb = blockIdx.x * 128;
    const int tid = threadIdx.x, lane = tid & 31, wid = tid >> 5;
    const int wm = wid >> 2, wn = wid & 3;

    extern __shared__ __align__(16) char dyn[];
    uint32_t sbase = smem_u32(dyn);
    uint32_t sA[2] = { sbase, sbase + TILEB };
    uint32_t sB[2] = { sbase + 2 * TILEB, sbase + 3 * TILEB };

    const float* Qg = g_Qt + ((size_t)b * NN + qb) * DD;
    const float* Kg = g_Kt + ((size_t)b * NN + kb) * DD;

    const int lr = lane & 7, lg = (lane >> 3) & 1, lh = lane >> 4;
    uint32_t a_off[4], b_off[4];
#pragma unroll
    for (int i = 0; i < 4; i++)
        a_off[i] = (uint32_t)(wm * 64 + i * 16 + lr + lg * 8) * 144 + (uint32_t)lh * 16;
#pragma unroll
    for (int j = 0; j < 4; j++)
        b_off[j] = (uint32_t)(wn * 32 + j * 8 + lr) * 144 + (uint32_t)lg * 16;

    float acc[4][4][4];
#pragma unroll
    for (int i = 0; i < 4; i++)
#pragma unroll
        for (int j = 0; j < 4; j++)
#pragma unroll
            for (int t = 0; t < 4; t++) acc[i][j][t] = 0.0f;

    load_t128_256(sA[0], Qg, DD, tid);
    load_t128_256(sB[0], Kg, DD, tid);
    CP_COMMIT();

#pragma unroll 1
    for (int c = 0; c < 4; c++) {
        CP_WAIT(0);
        __syncthreads();
        if (c + 1 < 4) {
            load_t128_256(sA[(c + 1) & 1], Qg + (c + 1) * 32, DD, tid);
            load_t128_256(sB[(c + 1) & 1], Kg + (c + 1) * 32, DD, tid);
            CP_COMMIT();
        }
        const uint32_t Ab = sA[c & 1], Bb = sB[c & 1];
#pragma unroll
        for (int ks = 0; ks < 4; ks++) {
            const uint32_t k0b = ks * 32;
            uint32_t af[4][4], bf[4][2];
#pragma unroll
            for (int i = 0; i < 4; i++) ldsm_x4(af[i], Ab + a_off[i] + k0b);
#pragma unroll
            for (int j = 0; j < 4; j++) ldsm_x2(bf[j], Bb + b_off[j] + k0b);
#pragma unroll
            for (int i = 0; i < 4; i++)
#pragma unroll
                for (int j = 0; j < 4; j++) mma_tf32(acc[i][j], af[i], bf[j]);
        }
    }

    const float SCALE = 0.08838834764831845f;
    float csum[4][2];
#pragma unroll
    for (int j = 0; j < 4; j++) { csum[j][0] = 0.0f; csum[j][1] = 0.0f; }

#pragma unroll
    for (int i = 0; i < 4; i++) {
        const int row0 = qb + wm * 64 + i * 16 + (lane >> 2);
#pragma unroll
        for (int j = 0; j < 4; j++) {
            __half h0 = __float2half_rn(__expf(acc[i][j][0] * SCALE));
            __half h1 = __float2half_rn(__expf(acc[i][j][1] * SCALE));
            __half h2 = __float2half_rn(__expf(acc[i][j][2] * SCALE));
            __half h3 = __float2half_rn(__expf(acc[i][j][3] * SCALE));
            const int col = kb + wn * 32 + j * 8 + (lane & 3) * 2;
            *(__half2*)(g_Eh + ((size_t)b * NN + row0) * NN + col)     = __halves2half2(h0, h1);
            *(__half2*)(g_Eh + ((size_t)b * NN + row0 + 8) * NN + col) = __halves2half2(h2, h3);
            csum[j][0] += __half2float(h0) + __half2float(h2);
            csum[j][1] += __half2float(h1) + __half2float(h3);
        }
    }
#pragma unroll
    for (int j = 0; j < 4; j++) {
#pragma unroll
        for (int p = 0; p < 2; p++) {
            float v = csum[j][p];
            v += __shfl_xor_sync(0xffffffffu, v, 4);
            v += __shfl_xor_sync(0xffffffffu, v, 8);
            v += __shfl_xor_sync(0xffffffffu, v, 16);
            if (lane < 4)
                atomicAdd(&g_l[b * NN + kb + wn * 32 + j * 8 + lane * 2 + p], v);
        }
    }
}

// ---------------- kernel 2: partial O = E_norm @ V (fp16 MMA) ----------------
// grid (64 qt, KSPLIT, 4 b), 128 threads (4 warps), tile 64(q) x 128(d), warp 64x32,
// 16 chunks of 32 k-halves, 2-stage, single sync per iteration, occ 4.
#define TILEA_H (64 * 80)    // 5120
#define TILEB_H (128 * 80)   // 10240
#define SM2 (2 * (TILEA_H + TILEB_H))  // 30720
__global__ __launch_bounds__(128, 4) void pv_kernel() {
    const int b = blockIdx.z, split = blockIdx.y, qb = blockIdx.x * 64;
    const int tid = threadIdx.x, lane = tid & 31, wn = tid >> 5;
    const int c0 = split * CHUNKS_PER_SPLIT;

    extern __shared__ __align__(16) char dyn[];
    uint32_t sbase = smem_u32(dyn);
    uint32_t sA[2] = { sbase, sbase + TILEA_H };
    uint32_t sB[2] = { sbase + 2 * TILEA_H, sbase + 2 * TILEA_H + TILEB_H };

    const __half* Eg = g_Eh + ((size_t)b * NN + qb) * NN;
    const __half* Vg = g_VTh + (size_t)b * DD * NN;

    // fp16 ldmatrix offsets, 80B row stride
    uint32_t a_off[4], b_off[4];
#pragma unroll
    for (int i = 0; i < 4; i++)
        a_off[i] = (uint32_t)(i * 16 + (lane & 15)) * 80 + (uint32_t)(lane >> 4) * 16;
#pragma unroll
    for (int j = 0; j < 4; j++)
        b_off[j] = (uint32_t)(wn * 32 + j * 8 + (lane & 7)) * 80 + (uint32_t)((lane >> 3) & 1) * 16;

    float acc[4][4][4];
#pragma unroll
    for (int i = 0; i < 4; i++)
#pragma unroll
        for (int j = 0; j < 4; j++)
#pragma unroll
            for (int t = 0; t < 4; t++) acc[i][j][t] = 0.0f;

    load_h64_128(sA[0], Eg + (size_t)c0 * 32, NN, tid);
    load_h128_128(sB[0], Vg + (size_t)c0 * 32, NN, tid);
    CP_COMMIT();

#pragma unroll 1
    for (int c = 0; c < CHUNKS_PER_SPLIT; c++) {
        CP_WAIT(0);
        __syncthreads();
        if (c + 1 < CHUNKS_PER_SPLIT) {
            load_h64_128(sA[(c + 1) & 1], Eg + (size_t)(c0 + c + 1) * 32, NN, tid);
            load_h128_128(sB[(c + 1) & 1], Vg + (size_t)(c0 + c + 1) * 32, NN, tid);
            CP_COMMIT();
        }
        const uint32_t Ab = sA[c & 1], Bb = sB[c & 1];
#pragma unroll
        for (int ks = 0; ks < 2; ks++) {           // two k16 steps per 32-chunk
            const uint32_t k0b = ks * 32;          // 16 halves = 32B
            uint32_t af[4][4], bf[4][2];
#pragma unroll
            for (int i = 0; i < 4; i++) ldsm_x4(af[i], Ab + a_off[i] + k0b);
#pragma unroll
            for (int j = 0; j < 4; j++) ldsm_x2(bf[j], Bb + b_off[j] + k0b);
#pragma unroll
            for (int i = 0; i < 4; i++)
#pragma unroll
                for (int j = 0; j < 4; j++) mma_f16(acc[i][j], af[i], bf[j]);
        }
    }

    float* Po = g_Po + (size_t)split * BB * NN * DD;
#pragma unroll
    for (int i = 0; i < 4; i++) {
        const int row0 = qb + i * 16 + (lane >> 2);
#pragma unroll
        for (int j = 0; j < 4; j++) {
            const int col = wn * 32 + j * 8 + (lane & 3) * 2;
            float2* p0 = (float2*)(Po + ((size_t)b * NN + row0) * DD + col);
            float2* p1 = (float2*)(Po + ((size_t)b * NN + row0 + 8) * DD + col);
            *p0 = make_float2(acc[i][j][0], acc[i][j][1]);
            *p1 = make_float2(acc[i][j][2], acc[i][j][3]);
        }
    }
}

// ---------------- launch ----------------
extern "C" void kernel_launch(void* const* d_in, const int* in_sizes, int n_in,
                              void* d_out, int out_size) {
    const float* q = (const float*)d_in[0];
    const float* k = (const float*)d_in[1];
    const float* v = (const float*)d_in[2];
    float* out = (float*)d_out;

    cudaFuncSetAttribute(qk_exp_kernel, cudaFuncAttributeMaxDynamicSharedMemorySize, SM1);
    cudaFuncSetAttribute(pv_kernel, cudaFuncAttributeMaxDynamicSharedMemorySize, SM2);

    size_t nqk = (size_t)BB * NN * DD;
    cvt_kernel<<<(unsigned)((nqk + 255) / 256), 256>>>(q, k);

    qk_exp_kernel<<<dim3(NN / 128, NN / 128, BB), 256, SM1>>>();

    vt_kernel<<<dim3(NN / 32, DD / 32, BB), dim3(32, 8)>>>(v);

    pv_kernel<<<dim3(NN / 64, KSPLIT, BB), 128, SM2>>>();

    size_t nout = (size_t)BB * NN * DD;
    reduce_kernel<<<(unsigned)((nout / 4 + 255) / 256), 256>>>(out);
}

// round 12
// speedup vs baseline: 1.3502x; 1.0185x over previous
#include <cuda_runtime.h>
#include <cuda_fp16.h>
#include <math.h>
#include <stdint.h>

#define BB 4
#define NN 4096
#define DD 128
#define KSPLIT 8                 // pv split-K factor
#define CHUNKS_PER_SPLIT (128 / KSPLIT)  // 16 chunks of 32

// ---------------- scratch (device globals; allocation-free) ----------------
__device__ __half g_Eh[(size_t)BB * NN * NN];  // exp(S), fp16 (134 MB)
__device__ float g_l[BB * NN];                 // column sums over q (of fp16-rounded E)
__device__ float g_Qt[(size_t)BB * NN * DD];   // RNA-tf32 rounded Q
__device__ float g_Kt[(size_t)BB * NN * DD];   // RNA-tf32 rounded K
__device__ __half g_VTh[(size_t)BB * DD * NN]; // V^T scaled by 1/l, fp16
__device__ float g_Po[(size_t)KSPLIT * BB * NN * DD];  // pv split partials

// ---------------- helpers ----------------
__device__ __forceinline__ uint32_t smem_u32(const void* p) {
    uint32_t a;
    asm("{ .reg .u64 t; cvta.to.shared.u64 t, %1; cvt.u32.u64 %0, t; }" : "=r"(a) : "l"(p));
    return a;
}
__device__ __forceinline__ float to_tf32(float x) {
    uint32_t u;
    asm("cvt.rna.tf32.f32 %0, %1;" : "=r"(u) : "f"(x));
    return __uint_as_float(u);
}

#define CP_ASYNC16(s, g) asm volatile("cp.async.cg.shared.global [%0], [%1], 16;" :: "r"(s), "l"(g))
#define CP_COMMIT()      asm volatile("cp.async.commit_group;" ::: "memory")
#define CP_WAIT(n)       asm volatile("cp.async.wait_group %0;" :: "n"(n) : "memory")

// m16n8k8 tf32 MMA (qk)
__device__ __forceinline__ void mma_tf32(float* c, const uint32_t* a, const uint32_t* b) {
    asm volatile(
        "mma.sync.aligned.m16n8k8.row.col.f32.tf32.tf32.f32 "
        "{%0,%1,%2,%3}, {%4,%5,%6,%7}, {%8,%9}, {%0,%1,%2,%3};"
        : "+f"(c[0]), "+f"(c[1]), "+f"(c[2]), "+f"(c[3])
        : "r"(a[0]), "r"(a[1]), "r"(a[2]), "r"(a[3]), "r"(b[0]), "r"(b[1]));
}
// m16n8k16 fp16 MMA, fp32 accumulate (pv)
__device__ __forceinline__ void mma_f16(float* c, const uint32_t* a, const uint32_t* b) {
    asm volatile(
        "mma.sync.aligned.m16n8k16.row.col.f32.f16.f16.f32 "
        "{%0,%1,%2,%3}, {%4,%5,%6,%7}, {%8,%9}, {%0,%1,%2,%3};"
        : "+f"(c[0]), "+f"(c[1]), "+f"(c[2]), "+f"(c[3])
        : "r"(a[0]), "r"(a[1]), "r"(a[2]), "r"(a[3]), "r"(b[0]), "r"(b[1]));
}

__device__ __forceinline__ void ldsm_x4(uint32_t* r, uint32_t addr) {
    asm volatile("ldmatrix.sync.aligned.m8n8.x4.shared.b16 {%0,%1,%2,%3}, [%4];"
                 : "=r"(r[0]), "=r"(r[1]), "=r"(r[2]), "=r"(r[3]) : "r"(addr));
}
__device__ __forceinline__ void ldsm_x2(uint32_t* r, uint32_t addr) {
    asm volatile("ldmatrix.sync.aligned.m8n8.x2.shared.b16 {%0,%1}, [%2];"
                 : "=r"(r[0]), "=r"(r[1]) : "r"(addr));
}

// fp32 tiles (qk): rows x 32 floats, row stride 36 floats (144B)
__device__ __forceinline__ void load_t128_256(uint32_t sdst, const float* g, size_t rstride, int tid) {
#pragma unroll
    for (int i = 0; i < 4; i++) {
        int idx = i * 256 + tid;
        int row = idx >> 3, c4 = idx & 7;
        CP_ASYNC16(sdst + row * 144 + c4 * 16, g + (size_t)row * rstride + c4 * 4);
    }
}
// fp16 tiles (pv): rows x 32 halves (64B data), row stride 80B (conflict-free ldsm)
__device__ __forceinline__ void load_h64_128(uint32_t sdst, const __half* g, size_t rstride, int tid) {
#pragma unroll
    for (int i = 0; i < 2; i++) {
        int idx = i * 128 + tid;   // 256 chunks of 16B
        int row = idx >> 2, c4 = idx & 3;
        CP_ASYNC16(sdst + row * 80 + c4 * 16, g + (size_t)row * rstride + c4 * 8);
    }
}
__device__ __forceinline__ void load_h128_128(uint32_t sdst, const __half* g, size_t rstride, int tid) {
#pragma unroll
    for (int i = 0; i < 4; i++) {
        int idx = i * 128 + tid;   // 512 chunks of 16B
        int row = idx >> 2, c4 = idx & 3;
        CP_ASYNC16(sdst + row * 80 + c4 * 16, g + (size_t)row * rstride + c4 * 8);
    }
}

// ---------------- small kernels ----------------
__global__ void cvt_kernel(const float* __restrict__ Q, const float* __restrict__ K) {
    size_t n = (size_t)BB * NN * DD;
    size_t i = (size_t)blockIdx.x * blockDim.x + threadIdx.x;
    if (i < n) {
        g_Qt[i] = to_tf32(Q[i]);
        g_Kt[i] = to_tf32(K[i]);
    }
    if (i < BB * NN) g_l[i] = 0.0f;
}
// VT[b][d][k] = fp16(V[b][k][d] / l[b][k])
__global__ void vt_kernel(const float* __restrict__ V) {
    __shared__ float ts[32][33];
    int b = blockIdx.z, d0 = blockIdx.y * 32, k0 = blockIdx.x * 32;
    int tx = threadIdx.x, ty = threadIdx.y;
    const float* Vb = V + (size_t)b * NN * DD;
#pragma unroll
    for (int i = 0; i < 4; i++) {
        int r = ty + i * 8;
        ts[r][tx] = Vb[(size_t)(k0 + r) * DD + d0 + tx];
    }
    __syncthreads();
    float linv = 1.0f / g_l[b * NN + k0 + tx];
#pragma unroll
    for (int i = 0; i < 4; i++) {
        int d = ty + i * 8;
        g_VTh[((size_t)b * DD + d0 + d) * NN + k0 + tx] = __float2half_rn(ts[tx][d] * linv);
    }
}
// O = sum of KSPLIT partials (deterministic order)
__global__ void reduce_kernel(float* __restrict__ O) {
    size_t i = ((size_t)blockIdx.x * blockDim.x + threadIdx.x) * 4;
    const size_t stride = (size_t)BB * NN * DD;
    if (i < stride) {
        float4 s = *(const float4*)(g_Po + i);
#pragma unroll
        for (int p = 1; p < KSPLIT; p++) {
            float4 t = *(const float4*)(g_Po + (size_t)p * stride + i);
            s.x += t.x; s.y += t.y; s.z += t.z; s.w += t.w;
        }
        *(float4*)(O + i) = s;
    }
}

// ---------------- kernel 1: E = exp(QK^T/sqrt(D)) fp16, l = colsum(E) ----------------
// grid (32 kt, 32 qt, 4 b), 256 threads (8 warps, 2x4), tile 128x128, K=128 in 4 chunks.
// 3-stage cp.async pipeline, single sync per iteration.
#define TILEB (128 * 36 * 4)  // 18432
#define SM1 (6 * TILEB)       // 110592 (3 stages x (A+B))
__global__ __launch_bounds__(256, 2) void qk_exp_kernel() {
    const int b = blockIdx.z, qb = blockIdx.y * 128, kb = blockIdx.x * 128;
    const int tid = threadIdx.x, lane = tid & 31, wid = tid >> 5;
    const int wm = wid >> 2, wn = wid & 3;

    extern __shared__ __align__(16) char dyn[];
    uint32_t sbase = smem_u32(dyn);
    uint32_t sA[3] = { sbase, sbase + TILEB, sbase + 2 * TILEB };
    uint32_t sB[3] = { sbase + 3 * TILEB, sbase + 4 * TILEB, sbase + 5 * TILEB };

    const float* Qg = g_Qt + ((size_t)b * NN + qb) * DD;
    const float* Kg = g_Kt + ((size_t)b * NN + kb) * DD;

    const int lr = lane & 7, lg = (lane >> 3) & 1, lh = lane >> 4;
    uint32_t a_off[4], b_off[4];
#pragma unroll
    for (int i = 0; i < 4; i++)
        a_off[i] = (uint32_t)(wm * 64 + i * 16 + lr + lg * 8) * 144 + (uint32_t)lh * 16;
#pragma unroll
    for (int j = 0; j < 4; j++)
        b_off[j] = (uint32_t)(wn * 32 + j * 8 + lr) * 144 + (uint32_t)lg * 16;

    float acc[4][4][4];
#pragma unroll
    for (int i = 0; i < 4; i++)
#pragma unroll
        for (int j = 0; j < 4; j++)
#pragma unroll
            for (int t = 0; t < 4; t++) acc[i][j][t] = 0.0f;

    load_t128_256(sA[0], Qg, DD, tid);
    load_t128_256(sB[0], Kg, DD, tid);
    CP_COMMIT();
    load_t128_256(sA[1], Qg + 32, DD, tid);
    load_t128_256(sB[1], Kg + 32, DD, tid);
    CP_COMMIT();

    int s = 0, sn = 2;  // current stage, next-load stage
#pragma unroll 1
    for (int c = 0; c < 4; c++) {
        CP_WAIT(1);       // chunk c landed (chunk c+1 may still be in flight)
        __syncthreads();  // all warps see chunk c; stage sn free (read in iter c-1)
        if (c + 2 < 4) {
            load_t128_256(sA[sn], Qg + (c + 2) * 32, DD, tid);
            load_t128_256(sB[sn], Kg + (c + 2) * 32, DD, tid);
        }
        CP_COMMIT();      // uniform commit keeps WAIT(1) arithmetic exact
        const uint32_t Ab = sA[s], Bb = sB[s];
#pragma unroll
        for (int ks = 0; ks < 4; ks++) {
            const uint32_t k0b = ks * 32;
            uint32_t af[4][4], bf[4][2];
#pragma unroll
            for (int i = 0; i < 4; i++) ldsm_x4(af[i], Ab + a_off[i] + k0b);
#pragma unroll
            for (int j = 0; j < 4; j++) ldsm_x2(bf[j], Bb + b_off[j] + k0b);
#pragma unroll
            for (int i = 0; i < 4; i++)
#pragma unroll
                for (int j = 0; j < 4; j++) mma_tf32(acc[i][j], af[i], bf[j]);
        }
        s = (s + 1) % 3;
        sn = (sn + 1) % 3;
    }

    const float SCALE = 0.08838834764831845f;
    float csum[4][2];
#pragma unroll
    for (int j = 0; j < 4; j++) { csum[j][0] = 0.0f; csum[j][1] = 0.0f; }

#pragma unroll
    for (int i = 0; i < 4; i++) {
        const int row0 = qb + wm * 64 + i * 16 + (lane >> 2);
#pragma unroll
        for (int j = 0; j < 4; j++) {
            __half h0 = __float2half_rn(__expf(acc[i][j][0] * SCALE));
            __half h1 = __float2half_rn(__expf(acc[i][j][1] * SCALE));
            __half h2 = __float2half_rn(__expf(acc[i][j][2] * SCALE));
            __half h3 = __float2half_rn(__expf(acc[i][j][3] * SCALE));
            const int col = kb + wn * 32 + j * 8 + (lane & 3) * 2;
            *(__half2*)(g_Eh + ((size_t)b * NN + row0) * NN + col)     = __halves2half2(h0, h1);
            *(__half2*)(g_Eh + ((size_t)b * NN + row0 + 8) * NN + col) = __halves2half2(h2, h3);
            csum[j][0] += __half2float(h0) + __half2float(h2);
            csum[j][1] += __half2float(h1) + __half2float(h3);
        }
    }
#pragma unroll
    for (int j = 0; j < 4; j++) {
#pragma unroll
        for (int p = 0; p < 2; p++) {
            float v = csum[j][p];
            v += __shfl_xor_sync(0xffffffffu, v, 4);
            v += __shfl_xor_sync(0xffffffffu, v, 8);
            v += __shfl_xor_sync(0xffffffffu, v, 16);
            if (lane < 4)
                atomicAdd(&g_l[b * NN + kb + wn * 32 + j * 8 + lane * 2 + p], v);
        }
    }
}

// ---------------- kernel 2: partial O = E_norm @ V (fp16 MMA) ----------------
// grid (64 qt, KSPLIT, 4 b), 128 threads (4 warps), tile 64(q) x 128(d), warp 64x32,
// 16 chunks of 32 k-halves, 3-stage pipeline, single sync per iteration, occ 4.
#define TILEA_H (64 * 80)    // 5120
#define TILEB_H (128 * 80)   // 10240
#define SM2 (3 * (TILEA_H + TILEB_H))  // 46080
__global__ __launch_bounds__(128, 4) void pv_kernel() {
    const int b = blockIdx.z, split = blockIdx.y, qb = blockIdx.x * 64;
    const int tid = threadIdx.x, lane = tid & 31, wn = tid >> 5;
    const int c0 = split * CHUNKS_PER_SPLIT;

    extern __shared__ __align__(16) char dyn[];
    uint32_t sbase = smem_u32(dyn);
    uint32_t sA[3] = { sbase, sbase + TILEA_H, sbase + 2 * TILEA_H };
    uint32_t sB[3] = { sbase + 3 * TILEA_H, sbase + 3 * TILEA_H + TILEB_H,
                       sbase + 3 * TILEA_H + 2 * TILEB_H };

    const __half* Eg = g_Eh + ((size_t)b * NN + qb) * NN;
    const __half* Vg = g_VTh + (size_t)b * DD * NN;

    uint32_t a_off[4], b_off[4];
#pragma unroll
    for (int i = 0; i < 4; i++)
        a_off[i] = (uint32_t)(i * 16 + (lane & 15)) * 80 + (uint32_t)(lane >> 4) * 16;
#pragma unroll
    for (int j = 0; j < 4; j++)
        b_off[j] = (uint32_t)(wn * 32 + j * 8 + (lane & 7)) * 80 + (uint32_t)((lane >> 3) & 1) * 16;

    float acc[4][4][4];
#pragma unroll
    for (int i = 0; i < 4; i++)
#pragma unroll
        for (int j = 0; j < 4; j++)
#pragma unroll
            for (int t = 0; t < 4; t++) acc[i][j][t] = 0.0f;

    load_h64_128(sA[0], Eg + (size_t)c0 * 32, NN, tid);
    load_h128_128(sB[0], Vg + (size_t)c0 * 32, NN, tid);
    CP_COMMIT();
    load_h64_128(sA[1], Eg + (size_t)(c0 + 1) * 32, NN, tid);
    load_h128_128(sB[1], Vg + (size_t)(c0 + 1) * 32, NN, tid);
    CP_COMMIT();

    int s = 0, sn = 2;
#pragma unroll 1
    for (int c = 0; c < CHUNKS_PER_SPLIT; c++) {
        CP_WAIT(1);
        __syncthreads();
        if (c + 2 < CHUNKS_PER_SPLIT) {
            load_h64_128(sA[sn], Eg + (size_t)(c0 + c + 2) * 32, NN, tid);
            load_h128_128(sB[sn], Vg + (size_t)(c0 + c + 2) * 32, NN, tid);
        }
        CP_COMMIT();
        const uint32_t Ab = sA[s], Bb = sB[s];
#pragma unroll
        for (int ks = 0; ks < 2; ks++) {           // two k16 steps per 32-chunk
            const uint32_t k0b = ks * 32;          // 16 halves = 32B
            uint32_t af[4][4], bf[4][2];
#pragma unroll
            for (int i = 0; i < 4; i++) ldsm_x4(af[i], Ab + a_off[i] + k0b);
#pragma unroll
            for (int j = 0; j < 4; j++) ldsm_x2(bf[j], Bb + b_off[j] + k0b);
#pragma unroll
            for (int i = 0; i < 4; i++)
#pragma unroll
                for (int j = 0; j < 4; j++) mma_f16(acc[i][j], af[i], bf[j]);
        }
        s = (s + 1) % 3;
        sn = (sn + 1) % 3;
    }

    float* Po = g_Po + (size_t)split * BB * NN * DD;
#pragma unroll
    for (int i = 0; i < 4; i++) {
        const int row0 = qb + i * 16 + (lane >> 2);
#pragma unroll
        for (int j = 0; j < 4; j++) {
            const int col = wn * 32 + j * 8 + (lane & 3) * 2;
            float2* p0 = (float2*)(Po + ((size_t)b * NN + row0) * DD + col);
            float2* p1 = (float2*)(Po + ((size_t)b * NN + row0 + 8) * DD + col);
            *p0 = make_float2(acc[i][j][0], acc[i][j][1]);
            *p1 = make_float2(acc[i][j][2], acc[i][j][3]);
        }
    }
}

// ---------------- launch ----------------
extern "C" void kernel_launch(void* const* d_in, const int* in_sizes, int n_in,
                              void* d_out, int out_size) {
    const float* q = (const float*)d_in[0];
    const float* k = (const float*)d_in[1];
    const float* v = (const float*)d_in[2];
    float* out = (float*)d_out;

    cudaFuncSetAttribute(qk_exp_kernel, cudaFuncAttributeMaxDynamicSharedMemorySize, SM1);
    cudaFuncSetAttribute(pv_kernel, cudaFuncAttributeMaxDynamicSharedMemorySize, SM2);

    size_t nqk = (size_t)BB * NN * DD;
    cvt_kernel<<<(unsigned)((nqk + 255) / 256), 256>>>(q, k);

    qk_exp_kernel<<<dim3(NN / 128, NN / 128, BB), 256, SM1>>>();

    vt_kernel<<<dim3(NN / 32, DD / 32, BB), dim3(32, 8)>>>(v);

    pv_kernel<<<dim3(NN / 64, KSPLIT, BB), 128, SM2>>>();

    size_t nout = (size_t)BB * NN * DD;
    reduce_kernel<<<(unsigned)((nout / 4 + 255) / 256), 256>>>(out);
}

// round 13
// speedup vs baseline: 1.5166x; 1.1232x over previous
#include <cuda_runtime.h>
#include <cuda_fp16.h>
#include <math.h>
#include <stdint.h>

#define BB 4
#define NN 4096
#define DD 128
#define KSPLIT 8                 // pv split-K factor
#define CHUNKS_PER_SPLIT (128 / KSPLIT)  // 16 chunks of 32

// ---------------- scratch (device globals; allocation-free) ----------------
__device__ __half g_Eh[(size_t)BB * NN * NN];  // exp(S), fp16 (134 MB)
__device__ float g_l[BB * NN];                 // column sums over q (of fp16-rounded E)
__device__ __half g_Qh[(size_t)BB * NN * DD];  // fp16 Q
__device__ __half g_Kh[(size_t)BB * NN * DD];  // fp16 K
__device__ __half g_VTh[(size_t)BB * DD * NN]; // V^T scaled by 1/l, fp16
__device__ float g_Po[(size_t)KSPLIT * BB * NN * DD];  // pv split partials

// ---------------- helpers ----------------
__device__ __forceinline__ uint32_t smem_u32(const void* p) {
    uint32_t a;
    asm("{ .reg .u64 t; cvta.to.shared.u64 t, %1; cvt.u32.u64 %0, t; }" : "=r"(a) : "l"(p));
    return a;
}

#define CP_ASYNC16(s, g) asm volatile("cp.async.cg.shared.global [%0], [%1], 16;" :: "r"(s), "l"(g))
#define CP_COMMIT()      asm volatile("cp.async.commit_group;" ::: "memory")
#define CP_WAIT(n)       asm volatile("cp.async.wait_group %0;" :: "n"(n) : "memory")

// m16n8k16 fp16 MMA, fp32 accumulate
__device__ __forceinline__ void mma_f16(float* c, const uint32_t* a, const uint32_t* b) {
    asm volatile(
        "mma.sync.aligned.m16n8k16.row.col.f32.f16.f16.f32 "
        "{%0,%1,%2,%3}, {%4,%5,%6,%7}, {%8,%9}, {%0,%1,%2,%3};"
        : "+f"(c[0]), "+f"(c[1]), "+f"(c[2]), "+f"(c[3])
        : "r"(a[0]), "r"(a[1]), "r"(a[2]), "r"(a[3]), "r"(b[0]), "r"(b[1]));
}

__device__ __forceinline__ void ldsm_x4(uint32_t* r, uint32_t addr) {
    asm volatile("ldmatrix.sync.aligned.m8n8.x4.shared.b16 {%0,%1,%2,%3}, [%4];"
                 : "=r"(r[0]), "=r"(r[1]), "=r"(r[2]), "=r"(r[3]) : "r"(addr));
}
__device__ __forceinline__ void ldsm_x2(uint32_t* r, uint32_t addr) {
    asm volatile("ldmatrix.sync.aligned.m8n8.x2.shared.b16 {%0,%1}, [%2];"
                 : "=r"(r[0]), "=r"(r[1]) : "r"(addr));
}

// fp16 tiles: rows x 32 halves (64B data), row stride 80B (conflict-free ldsm)
__device__ __forceinline__ void load_h128_256(uint32_t sdst, const __half* g, size_t rstride, int tid) {
#pragma unroll
    for (int i = 0; i < 2; i++) {
        int idx = i * 256 + tid;   // 512 chunks of 16B
        int row = idx >> 2, c4 = idx & 3;
        CP_ASYNC16(sdst + row * 80 + c4 * 16, g + (size_t)row * rstride + c4 * 8);
    }
}
__device__ __forceinline__ void load_h64_128(uint32_t sdst, const __half* g, size_t rstride, int tid) {
#pragma unroll
    for (int i = 0; i < 2; i++) {
        int idx = i * 128 + tid;   // 256 chunks of 16B
        int row = idx >> 2, c4 = idx & 3;
        CP_ASYNC16(sdst + row * 80 + c4 * 16, g + (size_t)row * rstride + c4 * 8);
    }
}
__device__ __forceinline__ void load_h128_128(uint32_t sdst, const __half* g, size_t rstride, int tid) {
#pragma unroll
    for (int i = 0; i < 4; i++) {
        int idx = i * 128 + tid;   // 512 chunks of 16B
        int row = idx >> 2, c4 = idx & 3;
        CP_ASYNC16(sdst + row * 80 + c4 * 16, g + (size_t)row * rstride + c4 * 8);
    }
}

// ---------------- small kernels ----------------
__global__ void cvt_kernel(const float* __restrict__ Q, const float* __restrict__ K) {
    size_t n = (size_t)BB * NN * DD;
    size_t i = (size_t)blockIdx.x * blockDim.x + threadIdx.x;
    if (i < n) {
        g_Qh[i] = __float2half_rn(Q[i]);
        g_Kh[i] = __float2half_rn(K[i]);
    }
    if (i < BB * NN) g_l[i] = 0.0f;
}
// VT[b][d][k] = fp16(V[b][k][d] / l[b][k])
__global__ void vt_kernel(const float* __restrict__ V) {
    __shared__ float ts[32][33];
    int b = blockIdx.z, d0 = blockIdx.y * 32, k0 = blockIdx.x * 32;
    int tx = threadIdx.x, ty = threadIdx.y;
    const float* Vb = V + (size_t)b * NN * DD;
#pragma unroll
    for (int i = 0; i < 4; i++) {
        int r = ty + i * 8;
        ts[r][tx] = Vb[(size_t)(k0 + r) * DD + d0 + tx];
    }
    __syncthreads();
    float linv = 1.0f / g_l[b * NN + k0 + tx];
#pragma unroll
    for (int i = 0; i < 4; i++) {
        int d = ty + i * 8;
        g_VTh[((size_t)b * DD + d0 + d) * NN + k0 + tx] = __float2half_rn(ts[tx][d] * linv);
    }
}
// O = sum of KSPLIT partials (deterministic order)
__global__ void reduce_kernel(float* __restrict__ O) {
    size_t i = ((size_t)blockIdx.x * blockDim.x + threadIdx.x) * 4;
    const size_t stride = (size_t)BB * NN * DD;
    if (i < stride) {
        float4 s = *(const float4*)(g_Po + i);
#pragma unroll
        for (int p = 1; p < KSPLIT; p++) {
            float4 t = *(const float4*)(g_Po + (size_t)p * stride + i);
            s.x += t.x; s.y += t.y; s.z += t.z; s.w += t.w;
        }
        *(float4*)(O + i) = s;
    }
}

// ---------------- kernel 1: E = exp(QK^T/sqrt(D)) fp16, l = colsum(E) ----------------
// grid (32 kt, 32 qt, 4 b), 256 threads (8 warps, 2x4), tile 128x128, fp16 MMA,
// D=128 in 4 chunks of 32 halves, 3-stage pipeline, single sync per iteration.
#define TILE_H128 (128 * 80)   // 10240
#define SM1 (6 * TILE_H128)    // 61440
__global__ __launch_bounds__(256, 2) void qk_exp_kernel() {
    const int b = blockIdx.z, qb = blockIdx.y * 128, kb = blockIdx.x * 128;
    const int tid = threadIdx.x, lane = tid & 31, wid = tid >> 5;
    const int wm = wid >> 2, wn = wid & 3;

    extern __shared__ __align__(16) char dyn[];
    uint32_t sbase = smem_u32(dyn);
    uint32_t sA[3] = { sbase, sbase + TILE_H128, sbase + 2 * TILE_H128 };
    uint32_t sB[3] = { sbase + 3 * TILE_H128, sbase + 4 * TILE_H128, sbase + 5 * TILE_H128 };

    const __half* Qg = g_Qh + ((size_t)b * NN + qb) * DD;
    const __half* Kg = g_Kh + ((size_t)b * NN + kb) * DD;

    // fp16 ldmatrix offsets, 80B row stride (same scheme as pv)
    uint32_t a_off[4], b_off[4];
#pragma unroll
    for (int i = 0; i < 4; i++)
        a_off[i] = (uint32_t)(wm * 64 + i * 16 + (lane & 15)) * 80 + (uint32_t)(lane >> 4) * 16;
#pragma unroll
    for (int j = 0; j < 4; j++)
        b_off[j] = (uint32_t)(wn * 32 + j * 8 + (lane & 7)) * 80 + (uint32_t)((lane >> 3) & 1) * 16;

    float acc[4][4][4];
#pragma unroll
    for (int i = 0; i < 4; i++)
#pragma unroll
        for (int j = 0; j < 4; j++)
#pragma unroll
            for (int t = 0; t < 4; t++) acc[i][j][t] = 0.0f;

    load_h128_256(sA[0], Qg, DD, tid);
    load_h128_256(sB[0], Kg, DD, tid);
    CP_COMMIT();
    load_h128_256(sA[1], Qg + 32, DD, tid);
    load_h128_256(sB[1], Kg + 32, DD, tid);
    CP_COMMIT();

    int s = 0, sn = 2;
#pragma unroll 1
    for (int c = 0; c < 4; c++) {
        CP_WAIT(1);
        __syncthreads();
        if (c + 2 < 4) {
            load_h128_256(sA[sn], Qg + (c + 2) * 32, DD, tid);
            load_h128_256(sB[sn], Kg + (c + 2) * 32, DD, tid);
        }
        CP_COMMIT();
        const uint32_t Ab = sA[s], Bb = sB[s];
#pragma unroll
        for (int ks = 0; ks < 2; ks++) {           // two k16 steps per 32-chunk
            const uint32_t k0b = ks * 32;
            uint32_t af[4][4], bf[4][2];
#pragma unroll
            for (int i = 0; i < 4; i++) ldsm_x4(af[i], Ab + a_off[i] + k0b);
#pragma unroll
            for (int j = 0; j < 4; j++) ldsm_x2(bf[j], Bb + b_off[j] + k0b);
#pragma unroll
            for (int i = 0; i < 4; i++)
#pragma unroll
                for (int j = 0; j < 4; j++) mma_f16(acc[i][j], af[i], bf[j]);
        }
        s = (s + 1) % 3;
        sn = (sn + 1) % 3;
    }

    const float SCALE = 0.08838834764831845f;
    float csum[4][2];
#pragma unroll
    for (int j = 0; j < 4; j++) { csum[j][0] = 0.0f; csum[j][1] = 0.0f; }

#pragma unroll
    for (int i = 0; i < 4; i++) {
        const int row0 = qb + wm * 64 + i * 16 + (lane >> 2);
#pragma unroll
        for (int j = 0; j < 4; j++) {
            __half h0 = __float2half_rn(__expf(acc[i][j][0] * SCALE));
            __half h1 = __float2half_rn(__expf(acc[i][j][1] * SCALE));
            __half h2 = __float2half_rn(__expf(acc[i][j][2] * SCALE));
            __half h3 = __float2half_rn(__expf(acc[i][j][3] * SCALE));
            const int col = kb + wn * 32 + j * 8 + (lane & 3) * 2;
            *(__half2*)(g_Eh + ((size_t)b * NN + row0) * NN + col)     = __halves2half2(h0, h1);
            *(__half2*)(g_Eh + ((size_t)b * NN + row0 + 8) * NN + col) = __halves2half2(h2, h3);
            csum[j][0] += __half2float(h0) + __half2float(h2);
            csum[j][1] += __half2float(h1) + __half2float(h3);
        }
    }
#pragma unroll
    for (int j = 0; j < 4; j++) {
#pragma unroll
        for (int p = 0; p < 2; p++) {
            float v = csum[j][p];
            v += __shfl_xor_sync(0xffffffffu, v, 4);
            v += __shfl_xor_sync(0xffffffffu, v, 8);
            v += __shfl_xor_sync(0xffffffffu, v, 16);
            if (lane < 4)
                atomicAdd(&g_l[b * NN + kb + wn * 32 + j * 8 + lane * 2 + p], v);
        }
    }
}

// ---------------- kernel 2: partial O = E_norm @ V (fp16 MMA) ----------------
// grid (64 qt, KSPLIT, 4 b), 128 threads (4 warps), tile 64(q) x 128(d), warp 64x32,
// 16 chunks of 32 k-halves, 3-stage pipeline, single sync per iteration, occ 4.
#define TILEA_H (64 * 80)    // 5120
#define TILEB_H (128 * 80)   // 10240
#define SM2 (3 * (TILEA_H + TILEB_H))  // 46080
__global__ __launch_bounds__(128, 4) void pv_kernel() {
    const int b = blockIdx.z, split = blockIdx.y, qb = blockIdx.x * 64;
    const int tid = threadIdx.x, lane = tid & 31, wn = tid >> 5;
    const int c0 = split * CHUNKS_PER_SPLIT;

    extern __shared__ __align__(16) char dyn[];
    uint32_t sbase = smem_u32(dyn);
    uint32_t sA[3] = { sbase, sbase + TILEA_H, sbase + 2 * TILEA_H };
    uint32_t sB[3] = { sbase + 3 * TILEA_H, sbase + 3 * TILEA_H + TILEB_H,
                       sbase + 3 * TILEA_H + 2 * TILEB_H };

    const __half* Eg = g_Eh + ((size_t)b * NN + qb) * NN;
    const __half* Vg = g_VTh + (size_t)b * DD * NN;

    uint32_t a_off[4], b_off[4];
#pragma unroll
    for (int i = 0; i < 4; i++)
        a_off[i] = (uint32_t)(i * 16 + (lane & 15)) * 80 + (uint32_t)(lane >> 4) * 16;
#pragma unroll
    for (int j = 0; j < 4; j++)
        b_off[j] = (uint32_t)(wn * 32 + j * 8 + (lane & 7)) * 80 + (uint32_t)((lane >> 3) & 1) * 16;

    float acc[4][4][4];
#pragma unroll
    for (int i = 0; i < 4; i++)
#pragma unroll
        for (int j = 0; j < 4; j++)
#pragma unroll
            for (int t = 0; t < 4; t++) acc[i][j][t] = 0.0f;

    load_h64_128(sA[0], Eg + (size_t)c0 * 32, NN, tid);
    load_h128_128(sB[0], Vg + (size_t)c0 * 32, NN, tid);
    CP_COMMIT();
    load_h64_128(sA[1], Eg + (size_t)(c0 + 1) * 32, NN, tid);
    load_h128_128(sB[1], Vg + (size_t)(c0 + 1) * 32, NN, tid);
    CP_COMMIT();

    int s = 0, sn = 2;
#pragma unroll 1
    for (int c = 0; c < CHUNKS_PER_SPLIT; c++) {
        CP_WAIT(1);
        __syncthreads();
        if (c + 2 < CHUNKS_PER_SPLIT) {
            load_h64_128(sA[sn], Eg + (size_t)(c0 + c + 2) * 32, NN, tid);
            load_h128_128(sB[sn], Vg + (size_t)(c0 + c + 2) * 32, NN, tid);
        }
        CP_COMMIT();
        const uint32_t Ab = sA[s], Bb = sB[s];
#pragma unroll
        for (int ks = 0; ks < 2; ks++) {
            const uint32_t k0b = ks * 32;
            uint32_t af[4][4], bf[4][2];
#pragma unroll
            for (int i = 0; i < 4; i++) ldsm_x4(af[i], Ab + a_off[i] + k0b);
#pragma unroll
            for (int j = 0; j < 4; j++) ldsm_x2(bf[j], Bb + b_off[j] + k0b);
#pragma unroll
            for (int i = 0; i < 4; i++)
#pragma unroll
                for (int j = 0; j < 4; j++) mma_f16(acc[i][j], af[i], bf[j]);
        }
        s = (s + 1) % 3;
        sn = (sn + 1) % 3;
    }

    float* Po = g_Po + (size_t)split * BB * NN * DD;
#pragma unroll
    for (int i = 0; i < 4; i++) {
        const int row0 = qb + i * 16 + (lane >> 2);
#pragma unroll
        for (int j = 0; j < 4; j++) {
            const int col = wn * 32 + j * 8 + (lane & 3) * 2;
            float2* p0 = (float2*)(Po + ((size_t)b * NN + row0) * DD + col);
            float2* p1 = (float2*)(Po + ((size_t)b * NN + row0 + 8) * DD + col);
            *p0 = make_float2(acc[i][j][0], acc[i][j][1]);
            *p1 = make_float2(acc[i][j][2], acc[i][j][3]);
        }
    }
}

// ---------------- launch ----------------
extern "C" void kernel_launch(void* const* d_in, const int* in_sizes, int n_in,
                              void* d_out, int out_size) {
    const float* q = (const float*)d_in[0];
    const float* k = (const float*)d_in[1];
    const float* v = (const float*)d_in[2];
    float* out = (float*)d_out;

    cudaFuncSetAttribute(qk_exp_kernel, cudaFuncAttributeMaxDynamicSharedMemorySize, SM1);
    cudaFuncSetAttribute(pv_kernel, cudaFuncAttributeMaxDynamicSharedMemorySize, SM2);

    size_t nqk = (size_t)BB * NN * DD;
    cvt_kernel<<<(unsigned)((nqk + 255) / 256), 256>>>(q, k);

    qk_exp_kernel<<<dim3(NN / 128, NN / 128, BB), 256, SM1>>>();

    vt_kernel<<<dim3(NN / 32, DD / 32, BB), dim3(32, 8)>>>(v);

    pv_kernel<<<dim3(NN / 64, KSPLIT, BB), 128, SM2>>>();

    size_t nout = (size_t)BB * NN * DD;
    reduce_kernel<<<(unsigned)((nout / 4 + 255) / 256), 256>>>(out);
}

// round 14
// speedup vs baseline: 1.5675x; 1.0335x over previous
#include <cuda_runtime.h>
#include <cuda_fp16.h>
#include <math.h>
#include <stdint.h>

#define BB 4
#define NN 4096
#define DD 128
#define KSPLIT 8                 // pv split-K factor
#define CHUNKS_PER_SPLIT (128 / KSPLIT)  // 16 chunks of 32

// ---------------- scratch (device globals; allocation-free) ----------------
__device__ __half g_Eh[(size_t)BB * NN * NN];  // exp(S), fp16 (134 MB)
__device__ float g_l[BB * NN];                 // column sums over q (of fp16-rounded E)
__device__ __half g_Qh[(size_t)BB * NN * DD];  // fp16 Q
__device__ __half g_Kh[(size_t)BB * NN * DD];  // fp16 K
__device__ __half g_VTh[(size_t)BB * DD * NN]; // V^T scaled by 1/l, fp16
__device__ float g_Po[(size_t)KSPLIT * BB * NN * DD];  // pv split partials

// ---------------- helpers ----------------
__device__ __forceinline__ uint32_t smem_u32(const void* p) {
    uint32_t a;
    asm("{ .reg .u64 t; cvta.to.shared.u64 t, %1; cvt.u32.u64 %0, t; }" : "=r"(a) : "l"(p));
    return a;
}

#define CP_ASYNC16(s, g) asm volatile("cp.async.cg.shared.global [%0], [%1], 16;" :: "r"(s), "l"(g))
#define CP_COMMIT()      asm volatile("cp.async.commit_group;" ::: "memory")
#define CP_WAIT(n)       asm volatile("cp.async.wait_group %0;" :: "n"(n) : "memory")

// m16n8k16 fp16 MMA, fp32 accumulate
__device__ __forceinline__ void mma_f16(float* c, const uint32_t* a, const uint32_t* b) {
    asm volatile(
        "mma.sync.aligned.m16n8k16.row.col.f32.f16.f16.f32 "
        "{%0,%1,%2,%3}, {%4,%5,%6,%7}, {%8,%9}, {%0,%1,%2,%3};"
        : "+f"(c[0]), "+f"(c[1]), "+f"(c[2]), "+f"(c[3])
        : "r"(a[0]), "r"(a[1]), "r"(a[2]), "r"(a[3]), "r"(b[0]), "r"(b[1]));
}

__device__ __forceinline__ void ldsm_x4(uint32_t* r, uint32_t addr) {
    asm volatile("ldmatrix.sync.aligned.m8n8.x4.shared.b16 {%0,%1,%2,%3}, [%4];"
                 : "=r"(r[0]), "=r"(r[1]), "=r"(r[2]), "=r"(r[3]) : "r"(addr));
}
__device__ __forceinline__ void ldsm_x2(uint32_t* r, uint32_t addr) {
    asm volatile("ldmatrix.sync.aligned.m8n8.x2.shared.b16 {%0,%1}, [%2];"
                 : "=r"(r[0]), "=r"(r[1]) : "r"(addr));
}

// fp16 tiles: rows x 32 halves (64B data), row stride 80B (conflict-free ldsm)
__device__ __forceinline__ void load_h128_256(uint32_t sdst, const __half* g, size_t rstride, int tid) {
#pragma unroll
    for (int i = 0; i < 2; i++) {
        int idx = i * 256 + tid;   // 512 chunks of 16B
        int row = idx >> 2, c4 = idx & 3;
        CP_ASYNC16(sdst + row * 80 + c4 * 16, g + (size_t)row * rstride + c4 * 8);
    }
}
__device__ __forceinline__ void load_h64_128(uint32_t sdst, const __half* g, size_t rstride, int tid) {
#pragma unroll
    for (int i = 0; i < 2; i++) {
        int idx = i * 128 + tid;   // 256 chunks of 16B
        int row = idx >> 2, c4 = idx & 3;
        CP_ASYNC16(sdst + row * 80 + c4 * 16, g + (size_t)row * rstride + c4 * 8);
    }
}
__device__ __forceinline__ void load_h128_128(uint32_t sdst, const __half* g, size_t rstride, int tid) {
#pragma unroll
    for (int i = 0; i < 4; i++) {
        int idx = i * 128 + tid;   // 512 chunks of 16B
        int row = idx >> 2, c4 = idx & 3;
        CP_ASYNC16(sdst + row * 80 + c4 * 16, g + (size_t)row * rstride + c4 * 8);
    }
}

// ---------------- small kernels ----------------
__global__ void cvt_kernel(const float* __restrict__ Q, const float* __restrict__ K) {
    size_t n = (size_t)BB * NN * DD;
    size_t i = (size_t)blockIdx.x * blockDim.x + threadIdx.x;
    if (i < n) {
        g_Qh[i] = __float2half_rn(Q[i]);
        g_Kh[i] = __float2half_rn(K[i]);
    }
    if (i < BB * NN) g_l[i] = 0.0f;
}
// VT[b][d][k] = fp16(V[b][k][d] / l[b][k])
__global__ void vt_kernel(const float* __restrict__ V) {
    __shared__ float ts[32][33];
    int b = blockIdx.z, d0 = blockIdx.y * 32, k0 = blockIdx.x * 32;
    int tx = threadIdx.x, ty = threadIdx.y;
    const float* Vb = V + (size_t)b * NN * DD;
#pragma unroll
    for (int i = 0; i < 4; i++) {
        int r = ty + i * 8;
        ts[r][tx] = Vb[(size_t)(k0 + r) * DD + d0 + tx];
    }
    __syncthreads();
    float linv = 1.0f / g_l[b * NN + k0 + tx];
#pragma unroll
    for (int i = 0; i < 4; i++) {
        int d = ty + i * 8;
        g_VTh[((size_t)b * DD + d0 + d) * NN + k0 + tx] = __float2half_rn(ts[tx][d] * linv);
    }
}
// O = sum of KSPLIT partials (deterministic order)
__global__ void reduce_kernel(float* __restrict__ O) {
    size_t i = ((size_t)blockIdx.x * blockDim.x + threadIdx.x) * 4;
    const size_t stride = (size_t)BB * NN * DD;
    if (i < stride) {
        float4 s = *(const float4*)(g_Po + i);
#pragma unroll
        for (int p = 1; p < KSPLIT; p++) {
            float4 t = *(const float4*)(g_Po + (size_t)p * stride + i);
            s.x += t.x; s.y += t.y; s.z += t.z; s.w += t.w;
        }
        *(float4*)(O + i) = s;
    }
}

// ---------------- kernel 1: E = exp(QK^T/sqrt(D)) fp16, l = colsum(E) ----------------
// grid (32 kt, 32 qt, 4 b), 256 threads (8 warps, 2x4), tile 128x128, fp16 MMA,
// D=128 in 4 chunks of 32 halves, 3-stage pipeline; epilogue staged through SMEM
// (272B row stride: frag writes + 16B copy reads both bank-conflict-free).
#define TILE_H128 (128 * 80)   // 10240
#define SM1 (6 * TILE_H128)    // 61440 (also covers 128*272=34816 stage)
__global__ __launch_bounds__(256, 2) void qk_exp_kernel() {
    const int b = blockIdx.z, qb = blockIdx.y * 128, kb = blockIdx.x * 128;
    const int tid = threadIdx.x, lane = tid & 31, wid = tid >> 5;
    const int wm = wid >> 2, wn = wid & 3;

    extern __shared__ __align__(16) char dyn[];
    uint32_t sbase = smem_u32(dyn);
    uint32_t sA[3] = { sbase, sbase + TILE_H128, sbase + 2 * TILE_H128 };
    uint32_t sB[3] = { sbase + 3 * TILE_H128, sbase + 4 * TILE_H128, sbase + 5 * TILE_H128 };

    const __half* Qg = g_Qh + ((size_t)b * NN + qb) * DD;
    const __half* Kg = g_Kh + ((size_t)b * NN + kb) * DD;

    uint32_t a_off[4], b_off[4];
#pragma unroll
    for (int i = 0; i < 4; i++)
        a_off[i] = (uint32_t)(wm * 64 + i * 16 + (lane & 15)) * 80 + (uint32_t)(lane >> 4) * 16;
#pragma unroll
    for (int j = 0; j < 4; j++)
        b_off[j] = (uint32_t)(wn * 32 + j * 8 + (lane & 7)) * 80 + (uint32_t)((lane >> 3) & 1) * 16;

    float acc[4][4][4];
#pragma unroll
    for (int i = 0; i < 4; i++)
#pragma unroll
        for (int j = 0; j < 4; j++)
#pragma unroll
            for (int t = 0; t < 4; t++) acc[i][j][t] = 0.0f;

    load_h128_256(sA[0], Qg, DD, tid);
    load_h128_256(sB[0], Kg, DD, tid);
    CP_COMMIT();
    load_h128_256(sA[1], Qg + 32, DD, tid);
    load_h128_256(sB[1], Kg + 32, DD, tid);
    CP_COMMIT();

    int s = 0, sn = 2;
#pragma unroll 1
    for (int c = 0; c < 4; c++) {
        CP_WAIT(1);
        __syncthreads();
        if (c + 2 < 4) {
            load_h128_256(sA[sn], Qg + (c + 2) * 32, DD, tid);
            load_h128_256(sB[sn], Kg + (c + 2) * 32, DD, tid);
        }
        CP_COMMIT();
        const uint32_t Ab = sA[s], Bb = sB[s];
#pragma unroll
        for (int ks = 0; ks < 2; ks++) {
            const uint32_t k0b = ks * 32;
            uint32_t af[4][4], bf[4][2];
#pragma unroll
            for (int i = 0; i < 4; i++) ldsm_x4(af[i], Ab + a_off[i] + k0b);
#pragma unroll
            for (int j = 0; j < 4; j++) ldsm_x2(bf[j], Bb + b_off[j] + k0b);
#pragma unroll
            for (int i = 0; i < 4; i++)
#pragma unroll
                for (int j = 0; j < 4; j++) mma_f16(acc[i][j], af[i], bf[j]);
        }
        s = (s + 1) % 3;
        sn = (sn + 1) % 3;
    }

    // ---- epilogue: exp -> fp16 -> SMEM stage -> coalesced global stores ----
    const float SCALE = 0.08838834764831845f;
    float csum[4][2];
#pragma unroll
    for (int j = 0; j < 4; j++) { csum[j][0] = 0.0f; csum[j][1] = 0.0f; }

    __syncthreads();  // all warps done reading pipeline smem; safe to reuse as stage
    // stage layout: 128 rows x 272B stride (128 halves data + 8 pad halves)
#pragma unroll
    for (int i = 0; i < 4; i++) {
        const int row0 = wm * 64 + i * 16 + (lane >> 2);
#pragma unroll
        for (int j = 0; j < 4; j++) {
            __half h0 = __float2half_rn(__expf(acc[i][j][0] * SCALE));
            __half h1 = __float2half_rn(__expf(acc[i][j][1] * SCALE));
            __half h2 = __float2half_rn(__expf(acc[i][j][2] * SCALE));
            __half h3 = __float2half_rn(__expf(acc[i][j][3] * SCALE));
            const int col = wn * 32 + j * 8 + (lane & 3) * 2;  // tile-local half idx
            *(__half2*)(dyn + row0 * 272 + col * 2)       = __halves2half2(h0, h1);
            *(__half2*)(dyn + (row0 + 8) * 272 + col * 2) = __halves2half2(h2, h3);
            csum[j][0] += __half2float(h0) + __half2float(h2);
            csum[j][1] += __half2float(h1) + __half2float(h3);
        }
    }
    __syncthreads();

    // coalesced copy: 8 iters x 256 threads x 16B; per row 16 threads write 256B
#pragma unroll
    for (int it = 0; it < 8; it++) {
        const int row = it * 16 + (tid >> 4);
        const int ch = tid & 15;
        uint4 v = *(const uint4*)(dyn + row * 272 + ch * 16);
        *(uint4*)(g_Eh + ((size_t)b * NN + qb + row) * NN + kb + ch * 8) = v;
    }

#pragma unroll
    for (int j = 0; j < 4; j++) {
#pragma unroll
        for (int p = 0; p < 2; p++) {
            float v = csum[j][p];
            v += __shfl_xor_sync(0xffffffffu, v, 4);
            v += __shfl_xor_sync(0xffffffffu, v, 8);
            v += __shfl_xor_sync(0xffffffffu, v, 16);
            if (lane < 4)
                atomicAdd(&g_l[b * NN + kb + wn * 32 + j * 8 + lane * 2 + p], v);
        }
    }
}

// ---------------- kernel 2: partial O = E_norm @ V (fp16 MMA) ----------------
// grid (64 qt, KSPLIT, 4 b), 128 threads (4 warps), tile 64(q) x 128(d), warp 64x32,
// 16 chunks of 32 k-halves, 3-stage pipeline, single sync per iteration, occ 4.
#define TILEA_H (64 * 80)    // 5120
#define TILEB_H (128 * 80)   // 10240
#define SM2 (3 * (TILEA_H + TILEB_H))  // 46080
__global__ __launch_bounds__(128, 4) void pv_kernel() {
    const int b = blockIdx.z, split = blockIdx.y, qb = blockIdx.x * 64;
    const int tid = threadIdx.x, lane = tid & 31, wn = tid >> 5;
    const int c0 = split * CHUNKS_PER_SPLIT;

    extern __shared__ __align__(16) char dyn[];
    uint32_t sbase = smem_u32(dyn);
    uint32_t sA[3] = { sbase, sbase + TILEA_H, sbase + 2 * TILEA_H };
    uint32_t sB[3] = { sbase + 3 * TILEA_H, sbase + 3 * TILEA_H + TILEB_H,
                       sbase + 3 * TILEA_H + 2 * TILEB_H };

    const __half* Eg = g_Eh + ((size_t)b * NN + qb) * NN;
    const __half* Vg = g_VTh + (size_t)b * DD * NN;

    uint32_t a_off[4], b_off[4];
#pragma unroll
    for (int i = 0; i < 4; i++)
        a_off[i] = (uint32_t)(i * 16 + (lane & 15)) * 80 + (uint32_t)(lane >> 4) * 16;
#pragma unroll
    for (int j = 0; j < 4; j++)
        b_off[j] = (uint32_t)(wn * 32 + j * 8 + (lane & 7)) * 80 + (uint32_t)((lane >> 3) & 1) * 16;

    float acc[4][4][4];
#pragma unroll
    for (int i = 0; i < 4; i++)
#pragma unroll
        for (int j = 0; j < 4; j++)
#pragma unroll
            for (int t = 0; t < 4; t++) acc[i][j][t] = 0.0f;

    load_h64_128(sA[0], Eg + (size_t)c0 * 32, NN, tid);
    load_h128_128(sB[0], Vg + (size_t)c0 * 32, NN, tid);
    CP_COMMIT();
    load_h64_128(sA[1], Eg + (size_t)(c0 + 1) * 32, NN, tid);
    load_h128_128(sB[1], Vg + (size_t)(c0 + 1) * 32, NN, tid);
    CP_COMMIT();

    int s = 0, sn = 2;
#pragma unroll 1
    for (int c = 0; c < CHUNKS_PER_SPLIT; c++) {
        CP_WAIT(1);
        __syncthreads();
        if (c + 2 < CHUNKS_PER_SPLIT) {
            load_h64_128(sA[sn], Eg + (size_t)(c0 + c + 2) * 32, NN, tid);
            load_h128_128(sB[sn], Vg + (size_t)(c0 + c + 2) * 32, NN, tid);
        }
        CP_COMMIT();
        const uint32_t Ab = sA[s], Bb = sB[s];
#pragma unroll
        for (int ks = 0; ks < 2; ks++) {
            const uint32_t k0b = ks * 32;
            uint32_t af[4][4], bf[4][2];
#pragma unroll
            for (int i = 0; i < 4; i++) ldsm_x4(af[i], Ab + a_off[i] + k0b);
#pragma unroll
            for (int j = 0; j < 4; j++) ldsm_x2(bf[j], Bb + b_off[j] + k0b);
#pragma unroll
            for (int i = 0; i < 4; i++)
#pragma unroll
                for (int j = 0; j < 4; j++) mma_f16(acc[i][j], af[i], bf[j]);
        }
        s = (s + 1) % 3;
        sn = (sn + 1) % 3;
    }

    float* Po = g_Po + (size_t)split * BB * NN * DD;
#pragma unroll
    for (int i = 0; i < 4; i++) {
        const int row0 = qb + i * 16 + (lane >> 2);
#pragma unroll
        for (int j = 0; j < 4; j++) {
            const int col = wn * 32 + j * 8 + (lane & 3) * 2;
            float2* p0 = (float2*)(Po + ((size_t)b * NN + row0) * DD + col);
            float2* p1 = (float2*)(Po + ((size_t)b * NN + row0 + 8) * DD + col);
            *p0 = make_float2(acc[i][j][0], acc[i][j][1]);
            *p1 = make_float2(acc[i][j][2], acc[i][j][3]);
        }
    }
}

// ---------------- launch ----------------
extern "C" void kernel_launch(void* const* d_in, const int* in_sizes, int n_in,
                              void* d_out, int out_size) {
    const float* q = (const float*)d_in[0];
    const float* k = (const float*)d_in[1];
    const float* v = (const float*)d_in[2];
    float* out = (float*)d_out;

    cudaFuncSetAttribute(qk_exp_kernel, cudaFuncAttributeMaxDynamicSharedMemorySize, SM1);
    cudaFuncSetAttribute(pv_kernel, cudaFuncAttributeMaxDynamicSharedMemorySize, SM2);

    size_t nqk = (size_t)BB * NN * DD;
    cvt_kernel<<<(unsigned)((nqk + 255) / 256), 256>>>(q, k);

    qk_exp_kernel<<<dim3(NN / 128, NN / 128, BB), 256, SM1>>>();

    vt_kernel<<<dim3(NN / 32, DD / 32, BB), dim3(32, 8)>>>(v);

    pv_kernel<<<dim3(NN / 64, KSPLIT, BB), 128, SM2>>>();

    size_t nout = (size_t)BB * NN * DD;
    reduce_kernel<<<(unsigned)((nout / 4 + 255) / 256), 256>>>(out);
}

// round 15
// speedup vs baseline: 1.5877x; 1.0129x over previous
#include <cuda_runtime.h>
#include <cuda_fp16.h>
#include <math.h>
#include <stdint.h>

#define BB 4
#define NN 4096
#define DD 128
#define KSPLIT 8                 // pv split-K factor
#define CHUNKS_PER_SPLIT (128 / KSPLIT)  // 16 chunks of 32

// ---------------- scratch (device globals; allocation-free) ----------------
__device__ __half g_Eh[(size_t)BB * NN * NN];  // exp(S), fp16 (134 MB)
__device__ float g_l[BB * NN];                 // column sums over q (of fp16-rounded E)
__device__ __half g_Qh[(size_t)BB * NN * DD];  // fp16 Q
__device__ __half g_Kh[(size_t)BB * NN * DD];  // fp16 K
__device__ __half g_VTh[(size_t)BB * DD * NN]; // V^T scaled by 1/l, fp16
__device__ __half g_Poh[(size_t)KSPLIT * BB * NN * DD];  // pv split partials (fp16)

// ---------------- helpers ----------------
__device__ __forceinline__ uint32_t smem_u32(const void* p) {
    uint32_t a;
    asm("{ .reg .u64 t; cvta.to.shared.u64 t, %1; cvt.u32.u64 %0, t; }" : "=r"(a) : "l"(p));
    return a;
}

#define CP_ASYNC16(s, g) asm volatile("cp.async.cg.shared.global [%0], [%1], 16;" :: "r"(s), "l"(g))
#define CP_COMMIT()      asm volatile("cp.async.commit_group;" ::: "memory")
#define CP_WAIT(n)       asm volatile("cp.async.wait_group %0;" :: "n"(n) : "memory")

// m16n8k16 fp16 MMA, fp32 accumulate
__device__ __forceinline__ void mma_f16(float* c, const uint32_t* a, const uint32_t* b) {
    asm volatile(
        "mma.sync.aligned.m16n8k16.row.col.f32.f16.f16.f32 "
        "{%0,%1,%2,%3}, {%4,%5,%6,%7}, {%8,%9}, {%0,%1,%2,%3};"
        : "+f"(c[0]), "+f"(c[1]), "+f"(c[2]), "+f"(c[3])
        : "r"(a[0]), "r"(a[1]), "r"(a[2]), "r"(a[3]), "r"(b[0]), "r"(b[1]));
}

__device__ __forceinline__ void ldsm_x4(uint32_t* r, uint32_t addr) {
    asm volatile("ldmatrix.sync.aligned.m8n8.x4.shared.b16 {%0,%1,%2,%3}, [%4];"
                 : "=r"(r[0]), "=r"(r[1]), "=r"(r[2]), "=r"(r[3]) : "r"(addr));
}
__device__ __forceinline__ void ldsm_x2(uint32_t* r, uint32_t addr) {
    asm volatile("ldmatrix.sync.aligned.m8n8.x2.shared.b16 {%0,%1}, [%2];"
                 : "=r"(r[0]), "=r"(r[1]) : "r"(addr));
}

// fp16 tiles: rows x 32 halves (64B data), row stride 80B (conflict-free ldsm)
__device__ __forceinline__ void load_h128_256(uint32_t sdst, const __half* g, size_t rstride, int tid) {
#pragma unroll
    for (int i = 0; i < 2; i++) {
        int idx = i * 256 + tid;   // 512 chunks of 16B
        int row = idx >> 2, c4 = idx & 3;
        CP_ASYNC16(sdst + row * 80 + c4 * 16, g + (size_t)row * rstride + c4 * 8);
    }
}
__device__ __forceinline__ void load_h64_128(uint32_t sdst, const __half* g, size_t rstride, int tid) {
#pragma unroll
    for (int i = 0; i < 2; i++) {
        int idx = i * 128 + tid;   // 256 chunks of 16B
        int row = idx >> 2, c4 = idx & 3;
        CP_ASYNC16(sdst + row * 80 + c4 * 16, g + (size_t)row * rstride + c4 * 8);
    }
}
__device__ __forceinline__ void load_h128_128(uint32_t sdst, const __half* g, size_t rstride, int tid) {
#pragma unroll
    for (int i = 0; i < 4; i++) {
        int idx = i * 128 + tid;   // 512 chunks of 16B
        int row = idx >> 2, c4 = idx & 3;
        CP_ASYNC16(sdst + row * 80 + c4 * 16, g + (size_t)row * rstride + c4 * 8);
    }
}

// ---------------- small kernels ----------------
__global__ void cvt_kernel(const float* __restrict__ Q, const float* __restrict__ K) {
    size_t n = (size_t)BB * NN * DD;
    size_t i = (size_t)blockIdx.x * blockDim.x + threadIdx.x;
    if (i < n) {
        g_Qh[i] = __float2half_rn(Q[i]);
        g_Kh[i] = __float2half_rn(K[i]);
    }
    if (i < BB * NN) g_l[i] = 0.0f;
}
// VT[b][d][k] = fp16(V[b][k][d] / l[b][k])
__global__ void vt_kernel(const float* __restrict__ V) {
    __shared__ float ts[32][33];
    int b = blockIdx.z, d0 = blockIdx.y * 32, k0 = blockIdx.x * 32;
    int tx = threadIdx.x, ty = threadIdx.y;
    const float* Vb = V + (size_t)b * NN * DD;
#pragma unroll
    for (int i = 0; i < 4; i++) {
        int r = ty + i * 8;
        ts[r][tx] = Vb[(size_t)(k0 + r) * DD + d0 + tx];
    }
    __syncthreads();
    float linv = 1.0f / g_l[b * NN + k0 + tx];
#pragma unroll
    for (int i = 0; i < 4; i++) {
        int d = ty + i * 8;
        g_VTh[((size_t)b * DD + d0 + d) * NN + k0 + tx] = __float2half_rn(ts[tx][d] * linv);
    }
}
// O = sum of KSPLIT fp16 partials (deterministic order), 8 elems per thread
__global__ void reduce_kernel(float* __restrict__ O) {
    size_t i = ((size_t)blockIdx.x * blockDim.x + threadIdx.x) * 8;
    const size_t stride = (size_t)BB * NN * DD;
    if (i < stride) {
        float s[8];
#pragma unroll
        for (int t = 0; t < 8; t++) s[t] = 0.0f;
#pragma unroll
        for (int p = 0; p < KSPLIT; p++) {
            uint4 v = *(const uint4*)(g_Poh + (size_t)p * stride + i);
            const __half2* h = (const __half2*)&v;
#pragma unroll
            for (int t = 0; t < 4; t++) {
                float2 f = __half22float2(h[t]);
                s[t * 2 + 0] += f.x;
                s[t * 2 + 1] += f.y;
            }
        }
        *(float4*)(O + i)     = make_float4(s[0], s[1], s[2], s[3]);
        *(float4*)(O + i + 4) = make_float4(s[4], s[5], s[6], s[7]);
    }
}

// ---------------- kernel 1: E = exp(QK^T/sqrt(D)) fp16, l = colsum(E) ----------------
// grid (32 kt, 32 qt, 4 b), 256 threads (8 warps, 2x4), tile 128x128, fp16 MMA,
// D=128 in 4 chunks of 32 halves, 3-stage pipeline; epilogue staged through SMEM.
#define TILE_H128 (128 * 80)   // 10240
#define SM1 (6 * TILE_H128)    // 61440 (also covers 128*272=34816 stage)
__global__ __launch_bounds__(256, 2) void qk_exp_kernel() {
    const int b = blockIdx.z, qb = blockIdx.y * 128, kb = blockIdx.x * 128;
    const int tid = threadIdx.x, lane = tid & 31, wid = tid >> 5;
    const int wm = wid >> 2, wn = wid & 3;

    extern __shared__ __align__(16) char dyn[];
    uint32_t sbase = smem_u32(dyn);
    uint32_t sA[3] = { sbase, sbase + TILE_H128, sbase + 2 * TILE_H128 };
    uint32_t sB[3] = { sbase + 3 * TILE_H128, sbase + 4 * TILE_H128, sbase + 5 * TILE_H128 };

    const __half* Qg = g_Qh + ((size_t)b * NN + qb) * DD;
    const __half* Kg = g_Kh + ((size_t)b * NN + kb) * DD;

    uint32_t a_off[4], b_off[4];
#pragma unroll
    for (int i = 0; i < 4; i++)
        a_off[i] = (uint32_t)(wm * 64 + i * 16 + (lane & 15)) * 80 + (uint32_t)(lane >> 4) * 16;
#pragma unroll
    for (int j = 0; j < 4; j++)
        b_off[j] = (uint32_t)(wn * 32 + j * 8 + (lane & 7)) * 80 + (uint32_t)((lane >> 3) & 1) * 16;

    float acc[4][4][4];
#pragma unroll
    for (int i = 0; i < 4; i++)
#pragma unroll
        for (int j = 0; j < 4; j++)
#pragma unroll
            for (int t = 0; t < 4; t++) acc[i][j][t] = 0.0f;

    load_h128_256(sA[0], Qg, DD, tid);
    load_h128_256(sB[0], Kg, DD, tid);
    CP_COMMIT();
    load_h128_256(sA[1], Qg + 32, DD, tid);
    load_h128_256(sB[1], Kg + 32, DD, tid);
    CP_COMMIT();

    int s = 0, sn = 2;
#pragma unroll 1
    for (int c = 0; c < 4; c++) {
        CP_WAIT(1);
        __syncthreads();
        if (c + 2 < 4) {
            load_h128_256(sA[sn], Qg + (c + 2) * 32, DD, tid);
            load_h128_256(sB[sn], Kg + (c + 2) * 32, DD, tid);
        }
        CP_COMMIT();
        const uint32_t Ab = sA[s], Bb = sB[s];
#pragma unroll
        for (int ks = 0; ks < 2; ks++) {
            const uint32_t k0b = ks * 32;
            uint32_t af[4][4], bf[4][2];
#pragma unroll
            for (int i = 0; i < 4; i++) ldsm_x4(af[i], Ab + a_off[i] + k0b);
#pragma unroll
            for (int j = 0; j < 4; j++) ldsm_x2(bf[j], Bb + b_off[j] + k0b);
#pragma unroll
            for (int i = 0; i < 4; i++)
#pragma unroll
                for (int j = 0; j < 4; j++) mma_f16(acc[i][j], af[i], bf[j]);
        }
        s = (s + 1) % 3;
        sn = (sn + 1) % 3;
    }

    // ---- epilogue: exp -> fp16 -> SMEM stage -> coalesced global stores ----
    const float SCALE = 0.08838834764831845f;
    float csum[4][2];
#pragma unroll
    for (int j = 0; j < 4; j++) { csum[j][0] = 0.0f; csum[j][1] = 0.0f; }

    __syncthreads();  // all warps done reading pipeline smem; safe to reuse as stage
#pragma unroll
    for (int i = 0; i < 4; i++) {
        const int row0 = wm * 64 + i * 16 + (lane >> 2);
#pragma unroll
        for (int j = 0; j < 4; j++) {
            __half h0 = __float2half_rn(__expf(acc[i][j][0] * SCALE));
            __half h1 = __float2half_rn(__expf(acc[i][j][1] * SCALE));
            __half h2 = __float2half_rn(__expf(acc[i][j][2] * SCALE));
            __half h3 = __float2half_rn(__expf(acc[i][j][3] * SCALE));
            const int col = wn * 32 + j * 8 + (lane & 3) * 2;
            *(__half2*)(dyn + row0 * 272 + col * 2)       = __halves2half2(h0, h1);
            *(__half2*)(dyn + (row0 + 8) * 272 + col * 2) = __halves2half2(h2, h3);
            csum[j][0] += __half2float(h0) + __half2float(h2);
            csum[j][1] += __half2float(h1) + __half2float(h3);
        }
    }
    __syncthreads();

#pragma unroll
    for (int it = 0; it < 8; it++) {
        const int row = it * 16 + (tid >> 4);
        const int ch = tid & 15;
        uint4 v = *(const uint4*)(dyn + row * 272 + ch * 16);
        *(uint4*)(g_Eh + ((size_t)b * NN + qb + row) * NN + kb + ch * 8) = v;
    }

#pragma unroll
    for (int j = 0; j < 4; j++) {
#pragma unroll
        for (int p = 0; p < 2; p++) {
            float v = csum[j][p];
            v += __shfl_xor_sync(0xffffffffu, v, 4);
            v += __shfl_xor_sync(0xffffffffu, v, 8);
            v += __shfl_xor_sync(0xffffffffu, v, 16);
            if (lane < 4)
                atomicAdd(&g_l[b * NN + kb + wn * 32 + j * 8 + lane * 2 + p], v);
        }
    }
}

// ---------------- kernel 2: partial O = E_norm @ V (fp16 MMA, fp16 partials) ----------------
// grid (64 qt, KSPLIT, 4 b), 128 threads (4 warps), tile 64(q) x 128(d), warp 64x32,
// 16 chunks of 32 k-halves, 3-stage pipeline, single sync per iteration, occ 4.
#define TILEA_H (64 * 80)    // 5120
#define TILEB_H (128 * 80)   // 10240
#define SM2 (3 * (TILEA_H + TILEB_H))  // 46080
__global__ __launch_bounds__(128, 4) void pv_kernel() {
    const int b = blockIdx.z, split = blockIdx.y, qb = blockIdx.x * 64;
    const int tid = threadIdx.x, lane = tid & 31, wn = tid >> 5;
    const int c0 = split * CHUNKS_PER_SPLIT;

    extern __shared__ __align__(16) char dyn[];
    uint32_t sbase = smem_u32(dyn);
    uint32_t sA[3] = { sbase, sbase + TILEA_H, sbase + 2 * TILEA_H };
    uint32_t sB[3] = { sbase + 3 * TILEA_H, sbase + 3 * TILEA_H + TILEB_H,
                       sbase + 3 * TILEA_H + 2 * TILEB_H };

    const __half* Eg = g_Eh + ((size_t)b * NN + qb) * NN;
    const __half* Vg = g_VTh + (size_t)b * DD * NN;

    uint32_t a_off[4], b_off[4];
#pragma unroll
    for (int i = 0; i < 4; i++)
        a_off[i] = (uint32_t)(i * 16 + (lane & 15)) * 80 + (uint32_t)(lane >> 4) * 16;
#pragma unroll
    for (int j = 0; j < 4; j++)
        b_off[j] = (uint32_t)(wn * 32 + j * 8 + (lane & 7)) * 80 + (uint32_t)((lane >> 3) & 1) * 16;

    float acc[4][4][4];
#pragma unroll
    for (int i = 0; i < 4; i++)
#pragma unroll
        for (int j = 0; j < 4; j++)
#pragma unroll
            for (int t = 0; t < 4; t++) acc[i][j][t] = 0.0f;

    load_h64_128(sA[0], Eg + (size_t)c0 * 32, NN, tid);
    load_h128_128(sB[0], Vg + (size_t)c0 * 32, NN, tid);
    CP_COMMIT();
    load_h64_128(sA[1], Eg + (size_t)(c0 + 1) * 32, NN, tid);
    load_h128_128(sB[1], Vg + (size_t)(c0 + 1) * 32, NN, tid);
    CP_COMMIT();

    int s = 0, sn = 2;
#pragma unroll 1
    for (int c = 0; c < CHUNKS_PER_SPLIT; c++) {
        CP_WAIT(1);
        __syncthreads();
        if (c + 2 < CHUNKS_PER_SPLIT) {
            load_h64_128(sA[sn], Eg + (size_t)(c0 + c + 2) * 32, NN, tid);
            load_h128_128(sB[sn], Vg + (size_t)(c0 + c + 2) * 32, NN, tid);
        }
        CP_COMMIT();
        const uint32_t Ab = sA[s], Bb = sB[s];
#pragma unroll
        for (int ks = 0; ks < 2; ks++) {
            const uint32_t k0b = ks * 32;
            uint32_t af[4][4], bf[4][2];
#pragma unroll
            for (int i = 0; i < 4; i++) ldsm_x4(af[i], Ab + a_off[i] + k0b);
#pragma unroll
            for (int j = 0; j < 4; j++) ldsm_x2(bf[j], Bb + b_off[j] + k0b);
#pragma unroll
            for (int i = 0; i < 4; i++)
#pragma unroll
                for (int j = 0; j < 4; j++) mma_f16(acc[i][j], af[i], bf[j]);
        }
        s = (s + 1) % 3;
        sn = (sn + 1) % 3;
    }

    __half* Po = g_Poh + (size_t)split * BB * NN * DD;
#pragma unroll
    for (int i = 0; i < 4; i++) {
        const int row0 = qb + i * 16 + (lane >> 2);
#pragma unroll
        for (int j = 0; j < 4; j++) {
            const int col = wn * 32 + j * 8 + (lane & 3) * 2;
            *(__half2*)(Po + ((size_t)b * NN + row0) * DD + col) =
                __floats2half2_rn(acc[i][j][0], acc[i][j][1]);
            *(__half2*)(Po + ((size_t)b * NN + row0 + 8) * DD + col) =
                __floats2half2_rn(acc[i][j][2], acc[i][j][3]);
        }
    }
}

// ---------------- launch ----------------
extern "C" void kernel_launch(void* const* d_in, const int* in_sizes, int n_in,
                              void* d_out, int out_size) {
    const float* q = (const float*)d_in[0];
    const float* k = (const float*)d_in[1];
    const float* v = (const float*)d_in[2];
    float* out = (float*)d_out;

    cudaFuncSetAttribute(qk_exp_kernel, cudaFuncAttributeMaxDynamicSharedMemorySize, SM1);
    cudaFuncSetAttribute(pv_kernel, cudaFuncAttributeMaxDynamicSharedMemorySize, SM2);

    size_t nqk = (size_t)BB * NN * DD;
    cvt_kernel<<<(unsigned)((nqk + 255) / 256), 256>>>(q, k);

    qk_exp_kernel<<<dim3(NN / 128, NN / 128, BB), 256, SM1>>>();

    vt_kernel<<<dim3(NN / 32, DD / 32, BB), dim3(32, 8)>>>(v);

    pv_kernel<<<dim3(NN / 64, KSPLIT, BB), 128, SM2>>>();

    size_t nout = (size_t)BB * NN * DD;
    reduce_kernel<<<(unsigned)((nout / 8 + 255) / 256), 256>>>(out);
}

// round 16
// speedup vs baseline: 1.7601x; 1.1086x over previous
#include <cuda_runtime.h>
#include <cuda_fp16.h>
#include <math.h>
#include <stdint.h>

#define BB 4
#define NN 4096
#define DD 128
#define KSPLIT 8                 // pv split-K factor
#define CHUNKS_PER_SPLIT 8       // 8 chunks of 64 halves = 512 per split

// ---------------- scratch (device globals; allocation-free) ----------------
__device__ __half g_Eh[(size_t)BB * NN * NN];  // exp(S), fp16 (134 MB)
__device__ float g_l[BB * NN];                 // column sums over q (of fp16-rounded E)
__device__ __half g_Qh[(size_t)BB * NN * DD];  // fp16 Q
__device__ __half g_Kh[(size_t)BB * NN * DD];  // fp16 K
__device__ __half g_VTh[(size_t)BB * DD * NN]; // V^T scaled by 1/l, fp16
__device__ __half g_Poh[(size_t)KSPLIT * BB * NN * DD];  // pv split partials (fp16)

// ---------------- helpers ----------------
__device__ __forceinline__ uint32_t smem_u32(const void* p) {
    uint32_t a;
    asm("{ .reg .u64 t; cvta.to.shared.u64 t, %1; cvt.u32.u64 %0, t; }" : "=r"(a) : "l"(p));
    return a;
}

#define CP_ASYNC16(s, g) asm volatile("cp.async.cg.shared.global [%0], [%1], 16;" :: "r"(s), "l"(g))
#define CP_COMMIT()      asm volatile("cp.async.commit_group;" ::: "memory")
#define CP_WAIT(n)       asm volatile("cp.async.wait_group %0;" :: "n"(n) : "memory")

// m16n8k16 fp16 MMA, fp32 accumulate
__device__ __forceinline__ void mma_f16(float* c, const uint32_t* a, const uint32_t* b) {
    asm volatile(
        "mma.sync.aligned.m16n8k16.row.col.f32.f16.f16.f32 "
        "{%0,%1,%2,%3}, {%4,%5,%6,%7}, {%8,%9}, {%0,%1,%2,%3};"
        : "+f"(c[0]), "+f"(c[1]), "+f"(c[2]), "+f"(c[3])
        : "r"(a[0]), "r"(a[1]), "r"(a[2]), "r"(a[3]), "r"(b[0]), "r"(b[1]));
}

__device__ __forceinline__ void ldsm_x4(uint32_t* r, uint32_t addr) {
    asm volatile("ldmatrix.sync.aligned.m8n8.x4.shared.b16 {%0,%1,%2,%3}, [%4];"
                 : "=r"(r[0]), "=r"(r[1]), "=r"(r[2]), "=r"(r[3]) : "r"(addr));
}
__device__ __forceinline__ void ldsm_x2(uint32_t* r, uint32_t addr) {
    asm volatile("ldmatrix.sync.aligned.m8n8.x2.shared.b16 {%0,%1}, [%2];"
                 : "=r"(r[0]), "=r"(r[1]) : "r"(addr));
}

// ---------------- small kernels ----------------
__global__ void cvt_kernel(const float* __restrict__ Q, const float* __restrict__ K) {
    size_t n = (size_t)BB * NN * DD;
    size_t i = (size_t)blockIdx.x * blockDim.x + threadIdx.x;
    if (i < n) {
        g_Qh[i] = __float2half_rn(Q[i]);
        g_Kh[i] = __float2half_rn(K[i]);
    }
    if (i < BB * NN) g_l[i] = 0.0f;
}
// VT[b][d][k] = fp16(V[b][k][d] / l[b][k])
__global__ void vt_kernel(const float* __restrict__ V) {
    __shared__ float ts[32][33];
    int b = blockIdx.z, d0 = blockIdx.y * 32, k0 = blockIdx.x * 32;
    int tx = threadIdx.x, ty = threadIdx.y;
    const float* Vb = V + (size_t)b * NN * DD;
#pragma unroll
    for (int i = 0; i < 4; i++) {
        int r = ty + i * 8;
        ts[r][tx] = Vb[(size_t)(k0 + r) * DD + d0 + tx];
    }
    __syncthreads();
    float linv = 1.0f / g_l[b * NN + k0 + tx];
#pragma unroll
    for (int i = 0; i < 4; i++) {
        int d = ty + i * 8;
        g_VTh[((size_t)b * DD + d0 + d) * NN + k0 + tx] = __float2half_rn(ts[tx][d] * linv);
    }
}
// O = sum of KSPLIT fp16 partials (deterministic order), 8 elems per thread
__global__ void reduce_kernel(float* __restrict__ O) {
    size_t i = ((size_t)blockIdx.x * blockDim.x + threadIdx.x) * 8;
    const size_t stride = (size_t)BB * NN * DD;
    if (i < stride) {
        float s[8];
#pragma unroll
        for (int t = 0; t < 8; t++) s[t] = 0.0f;
#pragma unroll
        for (int p = 0; p < KSPLIT; p++) {
            uint4 v = *(const uint4*)(g_Poh + (size_t)p * stride + i);
            const __half2* h = (const __half2*)&v;
#pragma unroll
            for (int t = 0; t < 4; t++) {
                float2 f = __half22float2(h[t]);
                s[t * 2 + 0] += f.x;
                s[t * 2 + 1] += f.y;
            }
        }
        *(float4*)(O + i)     = make_float4(s[0], s[1], s[2], s[3]);
        *(float4*)(O + i + 4) = make_float4(s[4], s[5], s[6], s[7]);
    }
}

// ---------------- kernel 1: E = exp(QK^T/sqrt(D)) fp16, l = colsum(E) ----------------
// grid (32 kt, 32 qt, 4 b), 256 threads (8 warps, 2x4), tile 128x128.
// Monolithic: whole 128x128-half Q and K tiles resident (272B row stride),
// ONE cp.async wait + ONE barrier, then 8 uninterrupted k16 MMA steps.
#define QK_TILE (128 * 272)   // 34816
#define SM1 (2 * QK_TILE)     // 69632
__global__ __launch_bounds__(256, 2) void qk_exp_kernel() {
    const int b = blockIdx.z, qb = blockIdx.y * 128, kb = blockIdx.x * 128;
    const int tid = threadIdx.x, lane = tid & 31, wid = tid >> 5;
    const int wm = wid >> 2, wn = wid & 3;

    extern __shared__ __align__(16) char dyn[];
    uint32_t sbase = smem_u32(dyn);
    const uint32_t sA = sbase, sB = sbase + QK_TILE;

    const __half* Qg = g_Qh + ((size_t)b * NN + qb) * DD;
    const __half* Kg = g_Kh + ((size_t)b * NN + kb) * DD;

    // full-tile loads: 128 rows x 256B = 2048 16B-chunks per tile, 8 per thread
#pragma unroll
    for (int i = 0; i < 8; i++) {
        int idx = i * 256 + tid;
        int row = idx >> 4, c4 = idx & 15;
        CP_ASYNC16(sA + row * 272 + c4 * 16, Qg + (size_t)row * DD + c4 * 8);
    }
#pragma unroll
    for (int i = 0; i < 8; i++) {
        int idx = i * 256 + tid;
        int row = idx >> 4, c4 = idx & 15;
        CP_ASYNC16(sB + row * 272 + c4 * 16, Kg + (size_t)row * DD + c4 * 8);
    }
    CP_COMMIT();

    // ldmatrix offsets, 272B row stride (68 words = 4 mod 32: conflict-free)
    uint32_t a_off[4], b_off[4];
#pragma unroll
    for (int i = 0; i < 4; i++)
        a_off[i] = (uint32_t)(wm * 64 + i * 16 + (lane & 15)) * 272 + (uint32_t)(lane >> 4) * 16;
#pragma unroll
    for (int j = 0; j < 4; j++)
        b_off[j] = (uint32_t)(wn * 32 + j * 8 + (lane & 7)) * 272 + (uint32_t)((lane >> 3) & 1) * 16;

    float acc[4][4][4];
#pragma unroll
    for (int i = 0; i < 4; i++)
#pragma unroll
        for (int j = 0; j < 4; j++)
#pragma unroll
            for (int t = 0; t < 4; t++) acc[i][j][t] = 0.0f;

    CP_WAIT(0);
    __syncthreads();

#pragma unroll
    for (int ks = 0; ks < 8; ks++) {
        const uint32_t k0b = ks * 32;   // 16 halves = 32B per k-step
        uint32_t af[4][4], bf[4][2];
#pragma unroll
        for (int i = 0; i < 4; i++) ldsm_x4(af[i], sA + a_off[i] + k0b);
#pragma unroll
        for (int j = 0; j < 4; j++) ldsm_x2(bf[j], sB + b_off[j] + k0b);
#pragma unroll
        for (int i = 0; i < 4; i++)
#pragma unroll
            for (int j = 0; j < 4; j++) mma_f16(acc[i][j], af[i], bf[j]);
    }

    // ---- epilogue: exp -> fp16 -> SMEM stage -> coalesced global stores ----
    const float SCALE = 0.08838834764831845f;
    float csum[4][2];
#pragma unroll
    for (int j = 0; j < 4; j++) { csum[j][0] = 0.0f; csum[j][1] = 0.0f; }

    __syncthreads();  // everyone done reading tiles; reuse smem as 128x272B stage
#pragma unroll
    for (int i = 0; i < 4; i++) {
        const int row0 = wm * 64 + i * 16 + (lane >> 2);
#pragma unroll
        for (int j = 0; j < 4; j++) {
            __half h0 = __float2half_rn(__expf(acc[i][j][0] * SCALE));
            __half h1 = __float2half_rn(__expf(acc[i][j][1] * SCALE));
            __half h2 = __float2half_rn(__expf(acc[i][j][2] * SCALE));
            __half h3 = __float2half_rn(__expf(acc[i][j][3] * SCALE));
            const int col = wn * 32 + j * 8 + (lane & 3) * 2;
            *(__half2*)(dyn + row0 * 272 + col * 2)       = __halves2half2(h0, h1);
            *(__half2*)(dyn + (row0 + 8) * 272 + col * 2) = __halves2half2(h2, h3);
            csum[j][0] += __half2float(h0) + __half2float(h2);
            csum[j][1] += __half2float(h1) + __half2float(h3);
        }
    }
    __syncthreads();

#pragma unroll
    for (int it = 0; it < 8; it++) {
        const int row = it * 16 + (tid >> 4);
        const int ch = tid & 15;
        uint4 v = *(const uint4*)(dyn + row * 272 + ch * 16);
        *(uint4*)(g_Eh + ((size_t)b * NN + qb + row) * NN + kb + ch * 8) = v;
    }

#pragma unroll
    for (int j = 0; j < 4; j++) {
#pragma unroll
        for (int p = 0; p < 2; p++) {
            float v = csum[j][p];
            v += __shfl_xor_sync(0xffffffffu, v, 4);
            v += __shfl_xor_sync(0xffffffffu, v, 8);
            v += __shfl_xor_sync(0xffffffffu, v, 16);
            if (lane < 4)
                atomicAdd(&g_l[b * NN + kb + wn * 32 + j * 8 + lane * 2 + p], v);
        }
    }
}

// ---------------- kernel 2: partial O = E_norm @ V (fp16 MMA, fp16 partials) ----------------
// grid (64 qt, KSPLIT, 4 b), 128 threads (4 warps), tile 64(q) x 128(d), warp 64x32,
// 8 chunks of 64 k-halves (144B rows), 2-stage, single sync per iteration, occ 4.
#define TILEA_H (64 * 144)    // 9216
#define TILEB_H (128 * 144)   // 18432
#define SM2 (2 * (TILEA_H + TILEB_H))  // 55296
__device__ __forceinline__ void pv_loadA(uint32_t sdst, const __half* g, int tid) {
#pragma unroll
    for (int i = 0; i < 4; i++) {
        int idx = i * 128 + tid;   // 512 chunks: 64 rows x 8
        int row = idx >> 3, c4 = idx & 7;
        CP_ASYNC16(sdst + row * 144 + c4 * 16, g + (size_t)row * NN + c4 * 8);
    }
}
__device__ __forceinline__ void pv_loadB(uint32_t sdst, const __half* g, int tid) {
#pragma unroll
    for (int i = 0; i < 8; i++) {
        int idx = i * 128 + tid;   // 1024 chunks: 128 rows x 8
        int row = idx >> 3, c4 = idx & 7;
        CP_ASYNC16(sdst + row * 144 + c4 * 16, g + (size_t)row * NN + c4 * 8);
    }
}
__global__ __launch_bounds__(128, 4) void pv_kernel() {
    const int b = blockIdx.z, split = blockIdx.y, qb = blockIdx.x * 64;
    const int tid = threadIdx.x, lane = tid & 31, wn = tid >> 5;
    const int c0 = split * CHUNKS_PER_SPLIT;   // chunk index (64-half units)

    extern __shared__ __align__(16) char dyn[];
    uint32_t sbase = smem_u32(dyn);
    uint32_t sA[2] = { sbase, sbase + TILEA_H };
    uint32_t sB[2] = { sbase + 2 * TILEA_H, sbase + 2 * TILEA_H + TILEB_H };

    const __half* Eg = g_Eh + ((size_t)b * NN + qb) * NN;
    const __half* Vg = g_VTh + (size_t)b * DD * NN;

    // ldmatrix offsets, 144B row stride (36 words = 4 mod 32: conflict-free)
    uint32_t a_off[4], b_off[4];
#pragma unroll
    for (int i = 0; i < 4; i++)
        a_off[i] = (uint32_t)(i * 16 + (lane & 15)) * 144 + (uint32_t)(lane >> 4) * 16;
#pragma unroll
    for (int j = 0; j < 4; j++)
        b_off[j] = (uint32_t)(wn * 32 + j * 8 + (lane & 7)) * 144 + (uint32_t)((lane >> 3) & 1) * 16;

    float acc[4][4][4];
#pragma unroll
    for (int i = 0; i < 4; i++)
#pragma unroll
        for (int j = 0; j < 4; j++)
#pragma unroll
            for (int t = 0; t < 4; t++) acc[i][j][t] = 0.0f;

    pv_loadA(sA[0], Eg + (size_t)c0 * 64, tid);
    pv_loadB(sB[0], Vg + (size_t)c0 * 64, tid);
    CP_COMMIT();

#pragma unroll 1
    for (int c = 0; c < CHUNKS_PER_SPLIT; c++) {
        CP_WAIT(0);
        __syncthreads();
        if (c + 1 < CHUNKS_PER_SPLIT) {
            pv_loadA(sA[(c + 1) & 1], Eg + (size_t)(c0 + c + 1) * 64, tid);
            pv_loadB(sB[(c + 1) & 1], Vg + (size_t)(c0 + c + 1) * 64, tid);
            CP_COMMIT();
        }
        const uint32_t Ab = sA[c & 1], Bb = sB[c & 1];
#pragma unroll
        for (int ks = 0; ks < 4; ks++) {           // four k16 steps per 64-chunk
            const uint32_t k0b = ks * 32;
            uint32_t af[4][4], bf[4][2];
#pragma unroll
            for (int i = 0; i < 4; i++) ldsm_x4(af[i], Ab + a_off[i] + k0b);
#pragma unroll
            for (int j = 0; j < 4; j++) ldsm_x2(bf[j], Bb + b_off[j] + k0b);
#pragma unroll
            for (int i = 0; i < 4; i++)
#pragma unroll
                for (int j = 0; j < 4; j++) mma_f16(acc[i][j], af[i], bf[j]);
        }
    }

    __half* Po = g_Poh + (size_t)split * BB * NN * DD;
#pragma unroll
    for (int i = 0; i < 4; i++) {
        const int row0 = qb + i * 16 + (lane >> 2);
#pragma unroll
        for (int j = 0; j < 4; j++) {
            const int col = wn * 32 + j * 8 + (lane & 3) * 2;
            *(__half2*)(Po + ((size_t)b * NN + row0) * DD + col) =
                __floats2half2_rn(acc[i][j][0], acc[i][j][1]);
            *(__half2*)(Po + ((size_t)b * NN + row0 + 8) * DD + col) =
                __floats2half2_rn(acc[i][j][2], acc[i][j][3]);
        }
    }
}

// ---------------- launch ----------------
extern "C" void kernel_launch(void* const* d_in, const int* in_sizes, int n_in,
                              void* d_out, int out_size) {
    const float* q = (const float*)d_in[0];
    const float* k = (const float*)d_in[1];
    const float* v = (const float*)d_in[2];
    float* out = (float*)d_out;

    cudaFuncSetAttribute(qk_exp_kernel, cudaFuncAttributeMaxDynamicSharedMemorySize, SM1);
    cudaFuncSetAttribute(pv_kernel, cudaFuncAttributeMaxDynamicSharedMemorySize, SM2);

    size_t nqk = (size_t)BB * NN * DD;
    cvt_kernel<<<(unsigned)((nqk + 255) / 256), 256>>>(q, k);

    qk_exp_kernel<<<dim3(NN / 128, NN / 128, BB), 256, SM1>>>();

    vt_kernel<<<dim3(NN / 32, DD / 32, BB), dim3(32, 8)>>>(v);

    pv_kernel<<<dim3(NN / 64, KSPLIT, BB), 128, SM2>>>();

    size_t nout = (size_t)BB * NN * DD;
    reduce_kernel<<<(unsigned)((nout / 8 + 255) / 256), 256>>>(out);
}